// round 14
// baseline (speedup 1.0000x reference)
#include <cuda_runtime.h>
#include <cuda_bf16.h>
#include <math.h>
#include <stdint.h>

// ---------------- problem constants ----------------
#define SEQ 128
#define BB  256
#define ED  512
#define FD  2048
#define NH  8
#define HD  64
#define NR  (SEQ*BB)   // 32768 rows
#define QKVW 1536      // fused qkv row width

static __device__ __forceinline__ float maxnorm() { return (float)(1.0 - 1e-5); }

// ---------------- scratch ----------------
__device__ float g_qkv[(size_t)NR*QKVW];
__device__ float g_o  [(size_t)NR*ED];
__device__ float g_h1 [(size_t)NR*ED];
__device__ float g_big[(size_t)NR*FD];
__device__ __nv_bfloat16 g_xh[(size_t)NR*FD];
__device__ __nv_bfloat16 g_xl[(size_t)NR*FD];
__device__ __nv_bfloat16 g_wh[(size_t)3*1024*1024];
__device__ __nv_bfloat16 g_wl[(size_t)3*1024*1024];
__device__ float g_n0 [NR];
__device__ float g_no [NR];
__device__ float g_nh2[NR];
__device__ float g_nh3[NR];
__device__ float g_b2 [8];

#define WQ0 0
#define WK0 262144
#define WV0 524288
#define WO0 786432
#define W10 1048576
#define W20 2097152

// ---------------- reductions ----------------
template <int T>
__device__ __forceinline__ float blockSumF(float v) {
    __shared__ float sh[T / 32];
    #pragma unroll
    for (int o = 16; o > 0; o >>= 1) v += __shfl_xor_sync(0xffffffffu, v, o);
    int lane = threadIdx.x & 31, w = threadIdx.x >> 5;
    if (lane == 0) sh[w] = v;
    __syncthreads();
    if (threadIdx.x < 32) {
        float t = (threadIdx.x < T / 32) ? sh[threadIdx.x] : 0.0f;
        #pragma unroll
        for (int o = 16; o > 0; o >>= 1) t += __shfl_xor_sync(0xffffffffu, t, o);
        if (threadIdx.x == 0) sh[0] = t;
    }
    __syncthreads();
    float r = sh[0];
    __syncthreads();
    return r;
}
__device__ __forceinline__ float warpSumF(float v) {
    #pragma unroll
    for (int o = 16; o > 0; o >>= 1) v += __shfl_xor_sync(0xffffffffu, v, o);
    return v;
}

__device__ __forceinline__ void split1(float x, __nv_bfloat16 &h, __nv_bfloat16 &l) {
    h = __float2bfloat16(x);
    l = __float2bfloat16(x - __bfloat162float(h));
}
__device__ __forceinline__ uint32_t pack_bf2(float a, float b) {
    __nv_bfloat162 t(__float2bfloat16(a), __float2bfloat16(b));
    return *(uint32_t*)&t;
}

// FMA-pipe exp (no MUFU)
__device__ __forceinline__ float fexp(float x) {
    float y = x * 1.4426950408889634f;
    y = fmaxf(y, -126.0f);
    float fl = floorf(y);
    float f = y - fl;
    float p = 1.5252734e-5f;
    p = fmaf(p, f, 1.5403530e-4f);
    p = fmaf(p, f, 1.3333558e-3f);
    p = fmaf(p, f, 9.6181291e-3f);
    p = fmaf(p, f, 5.5504109e-2f);
    p = fmaf(p, f, 2.4022651e-1f);
    p = fmaf(p, f, 6.9314718e-1f);
    p = fmaf(p, f, 1.0f);
    return __int_as_float(__float_as_int(p) + (((int)fl) << 23));
}

// vector helpers
#define VOP4(dst, ex, ey, ez, ew) do { dst.x=(ex); dst.y=(ey); dst.z=(ez); dst.w=(ew); } while(0)
__device__ __forceinline__ float dot4(float4 a, float4 b) { return a.x*b.x + a.y*b.y + a.z*b.z + a.w*b.w; }
__device__ __forceinline__ float sq4(float4 a) { return dot4(a, a); }
__device__ __forceinline__ float4 scl4(float4 a, float s) { float4 r; VOP4(r, a.x*s, a.y*s, a.z*s, a.w*s); return r; }

__device__ __forceinline__ void write_split4(float4 v, __nv_bfloat16* oh, __nv_bfloat16* ol, int idx2) {
    __nv_bfloat16 h0,l0,h1,l1,h2,l2,h3,l3;
    split1(v.x,h0,l0); split1(v.y,h1,l1); split1(v.z,h2,l2); split1(v.w,h3,l3);
    ((__nv_bfloat162*)oh)[idx2]   = __nv_bfloat162(h0,h1);
    ((__nv_bfloat162*)oh)[idx2+1] = __nv_bfloat162(h2,h3);
    ((__nv_bfloat162*)ol)[idx2]   = __nv_bfloat162(l0,l1);
    ((__nv_bfloat162*)ol)[idx2+1] = __nv_bfloat162(l2,l3);
}

// ================= fused prep: weight splits + bias norms + ln1 (one launch) =================
#define PREP_BLOCKS (3072 + 6 + NR/8)
__global__ void __launch_bounds__(256) prep_kernel(
    const float* Wq, const float* Wk, const float* Wv,
    const float* Wo, const float* W1, const float* W2,
    const float* bq, const float* bk, const float* bv,
    const float* bo, const float* b1, const float* b2,
    const float* __restrict__ x, const float* __restrict__ l1g, const float* __restrict__ l1b,
    __nv_bfloat16* __restrict__ wh, __nv_bfloat16* __restrict__ wl,
    __nv_bfloat16* __restrict__ xh, __nv_bfloat16* __restrict__ xl,
    float* __restrict__ n0out, float* __restrict__ bsq)
{
    const int bid = blockIdx.x;
    if (bid < 3072) {
        const float* src; size_t off; int sub;
        if (bid < 1024) {
            sub = bid & 255;
            switch (bid >> 8) {
                case 0: src = Wq; off = WQ0; break;
                case 1: src = Wk; off = WK0; break;
                case 2: src = Wv; off = WV0; break;
                default: src = Wo; off = WO0; break;
            }
        } else if (bid < 2048) { src = W1; off = W10; sub = bid - 1024; }
        else                   { src = W2; off = W20; sub = bid - 2048; }
        int i = sub * 256 + threadIdx.x;
        float4 v = ((const float4*)src)[i];
        __nv_bfloat16 h0,l0,h1,l1,h2,l2,h3,l3;
        split1(v.x, h0, l0); split1(v.y, h1, l1);
        split1(v.z, h2, l2); split1(v.w, h3, l3);
        __nv_bfloat162* hp = (__nv_bfloat162*)(wh + off);
        __nv_bfloat162* lp = (__nv_bfloat162*)(wl + off);
        hp[i*2]   = __nv_bfloat162(h0, h1);
        hp[i*2+1] = __nv_bfloat162(h2, h3);
        lp[i*2]   = __nv_bfloat162(l0, l1);
        lp[i*2+1] = __nv_bfloat162(l2, l3);
        return;
    }
    if (bid < 3078) {
        int task = bid - 3072;
        const float* p; int n;
        switch (task) {
            case 0: p = bq; n = ED; break;
            case 1: p = bk; n = ED; break;
            case 2: p = bv; n = ED; break;
            case 3: p = bo; n = ED; break;
            case 4: p = b1; n = FD; break;
            default: p = b2; n = ED; break;
        }
        float s = 0.0f;
        for (int i = threadIdx.x; i < n; i += 256) { float xx = p[i]; s += xx * xx; }
        s = blockSumF<256>(s);
        if (threadIdx.x == 0) bsq[task] = s;
        return;
    }
    // ln1 warp-per-row
    const int lane = threadIdx.x & 31;
    const size_t row = (size_t)(bid - 3078) * 8 + (threadIdx.x >> 5);
    const float MAXN = maxnorm();
    const float4* xp = (const float4*)(x + row * ED);
    float4 v[4];
    float ss = 0.0f;
    #pragma unroll
    for (int i = 0; i < 4; i++) { v[i] = xp[lane + i*32]; ss += sq4(v[i]); }
    float nn0 = sqrtf(warpSumF(ss) + 1e-30f);
    float lf = atanhf(fminf(nn0, MAXN)) / nn0;
    float sm = 0.0f;
    #pragma unroll
    for (int i = 0; i < 4; i++) { v[i] = scl4(v[i], lf); sm += v[i].x + v[i].y + v[i].z + v[i].w; }
    float mu = warpSumF(sm) * (1.0f / ED);
    float vv = 0.0f;
    #pragma unroll
    for (int i = 0; i < 4; i++) {
        float4 d; VOP4(d, v[i].x-mu, v[i].y-mu, v[i].z-mu, v[i].w-mu);
        vv += sq4(d);
    }
    float var = warpSumF(vv) * (1.0f / ED);
    float inv = rsqrtf(var + 1e-5f);
    float s2 = 0.0f;
    #pragma unroll
    for (int i = 0; i < 4; i++) {
        float4 gg = ((const float4*)l1g)[lane + i*32], bb = ((const float4*)l1b)[lane + i*32];
        VOP4(v[i], (v[i].x-mu)*inv*gg.x + bb.x, (v[i].y-mu)*inv*gg.y + bb.y,
                   (v[i].z-mu)*inv*gg.z + bb.z, (v[i].w-mu)*inv*gg.w + bb.w);
        s2 += sq4(v[i]);
    }
    float ny = sqrtf(warpSumF(s2) + 1e-30f);
    float ef = tanhf(ny) / ny;
    float s4 = 0.0f;
    #pragma unroll
    for (int i = 0; i < 4; i++) {
        v[i] = scl4(v[i], ef);
        write_split4(v[i], xh + row*ED, xl + row*ED, (lane + i*32)*2);
        s4 += sq4(v[i]);
    }
    float nf = sqrtf(warpSumF(s4) + 1e-30f);
    if (lane == 0) n0out[row] = nf;
}

// ================= warp-per-row kernels =================

// ---------------- expmap0 ----------------
__global__ void __launch_bounds__(256) expmap_w(
    const float* __restrict__ x, __nv_bfloat16* __restrict__ oh, __nv_bfloat16* __restrict__ ol,
    float* __restrict__ out_norm)
{
    const int lane = threadIdx.x & 31;
    const size_t row = blockIdx.x * 8 + (threadIdx.x >> 5);
    const float4* xp = (const float4*)(x + row * ED);
    float4 v[4];
    float ss = 0.0f;
    #pragma unroll
    for (int i = 0; i < 4; i++) { v[i] = xp[lane + i*32]; ss += sq4(v[i]); }
    float n = sqrtf(warpSumF(ss) + 1e-30f);
    float ef = tanhf(n) / n;
    float s2 = 0.0f;
    #pragma unroll
    for (int i = 0; i < 4; i++) {
        v[i] = scl4(v[i], ef);
        write_split4(v[i], oh + row*ED, ol + row*ED, (lane + i*32)*2);
        s2 += sq4(v[i]);
    }
    float nf = sqrtf(warpSumF(s2) + 1e-30f);
    if (lane == 0) out_norm[row] = nf;
}

// ---------------- q/k/v manifold epilogue ----------------
__global__ void __launch_bounds__(256) manlin_qkv_w(
    const float* __restrict__ qkvf, const float* __restrict__ xnb,
    const float* __restrict__ bq, const float* __restrict__ bk, const float* __restrict__ bv,
    __nv_bfloat16* __restrict__ oh, __nv_bfloat16* __restrict__ ol)
{
    const int lane = threadIdx.x & 31;
    const size_t row = blockIdx.x * 8 + (threadIdx.x >> 5);
    const int seg = blockIdx.y;
    const float MAXN = maxnorm();
    const float* bias = (seg == 0) ? bq : (seg == 1) ? bk : bv;
    const float4* base = (const float4*)(qkvf + row * (size_t)QKVW + seg * 512);
    float4 v[4], bvv[4];
    float ss = 0.0f;
    #pragma unroll
    for (int i = 0; i < 4; i++) {
        v[i] = base[lane + i*32];
        bvv[i] = ((const float4*)bias)[lane + i*32];
        ss += sq4(v[i]);
    }
    float mxn = sqrtf(warpSumF(ss) + 1e-30f);
    float xn = xnb[row];
    float s = tanhf(mxn / xn * atanhf(fminf(xn, MAXN))) / mxn;
    float dxy = 0.0f, dx2 = 0.0f;
    #pragma unroll
    for (int i = 0; i < 4; i++) {
        v[i] = scl4(v[i], s);
        dxy += dot4(v[i], bvv[i]);
        dx2 += sq4(v[i]);
    }
    float xy = warpSumF(dxy);
    float x2 = warpSumF(dx2);
    float y2 = g_b2[seg];
    float a = 1.0f + 2.0f*xy + y2;
    float c = 1.0f - x2;
    float invd = 1.0f / fmaxf(1.0f + 2.0f*xy + x2*y2, 1e-15f);
    float zz = 0.0f;
    #pragma unroll
    for (int i = 0; i < 4; i++) {
        VOP4(v[i], (a*v[i].x + c*bvv[i].x)*invd, (a*v[i].y + c*bvv[i].y)*invd,
                   (a*v[i].z + c*bvv[i].z)*invd, (a*v[i].w + c*bvv[i].w)*invd);
        zz += sq4(v[i]);
    }
    float zn = sqrtf(warpSumF(zz) + 1e-30f);
    if (zn > MAXN) {
        float ps = MAXN / zn;
        #pragma unroll
        for (int i = 0; i < 4; i++) v[i] = scl4(v[i], ps);
    }
    float s0 = 0.0f;
    #pragma unroll
    for (int i = 0; i < 4; i++) s0 += sq4(v[i]);
    float n = sqrtf(warpSumF(s0) + 1e-30f);
    float lf = atanhf(fminf(n, MAXN)) / n;
    size_t ob = row * (size_t)QKVW + seg * 512;
    #pragma unroll
    for (int i = 0; i < 4; i++) {
        v[i] = scl4(v[i], lf);
        write_split4(v[i], oh + ob, ol + ob, (lane + i*32)*2);
    }
}

// ---------------- fused: manlin(Wo)+residual -> ln2 -> splits ----------------
__global__ void __launch_bounds__(256) manlin_ln_w(
    const float* __restrict__ mx, const float* __restrict__ xnb,
    const float* __restrict__ bias, int b2idx, const float* __restrict__ resid,
    float* __restrict__ h1out,
    const float* __restrict__ g, const float* __restrict__ bln,
    __nv_bfloat16* __restrict__ oh, __nv_bfloat16* __restrict__ ol,
    float* __restrict__ out_norm)
{
    const int lane = threadIdx.x & 31;
    const size_t row = blockIdx.x * 8 + (threadIdx.x >> 5);
    const float MAXN = maxnorm();
    float4 v[4], bvv[4];
    float ss = 0.0f;
    #pragma unroll
    for (int i = 0; i < 4; i++) {
        v[i] = ((const float4*)(mx + row*ED))[lane + i*32];
        bvv[i] = ((const float4*)bias)[lane + i*32];
        ss += sq4(v[i]);
    }
    float mxn = sqrtf(warpSumF(ss) + 1e-30f);
    float xn = xnb[row];
    float s = tanhf(mxn / xn * atanhf(fminf(xn, MAXN))) / mxn;
    float dxy = 0.0f, dx2 = 0.0f;
    #pragma unroll
    for (int i = 0; i < 4; i++) {
        v[i] = scl4(v[i], s);
        dxy += dot4(v[i], bvv[i]);
        dx2 += sq4(v[i]);
    }
    float xy = warpSumF(dxy);
    float x2 = warpSumF(dx2);
    float y2 = g_b2[b2idx];
    float a = 1.0f + 2.0f*xy + y2;
    float c = 1.0f - x2;
    float invd = 1.0f / fmaxf(1.0f + 2.0f*xy + x2*y2, 1e-15f);
    float zz = 0.0f;
    #pragma unroll
    for (int i = 0; i < 4; i++) {
        VOP4(v[i], (a*v[i].x + c*bvv[i].x)*invd, (a*v[i].y + c*bvv[i].y)*invd,
                   (a*v[i].z + c*bvv[i].z)*invd, (a*v[i].w + c*bvv[i].w)*invd);
        zz += sq4(v[i]);
    }
    {
        float zn = sqrtf(warpSumF(zz) + 1e-30f);
        if (zn > MAXN) { float ps = MAXN / zn;
            #pragma unroll
            for (int i = 0; i < 4; i++) v[i] = scl4(v[i], ps); }
    }
    {
        float d1 = 0.0f, d2 = 0.0f, d3 = 0.0f;
        float4 rv[4];
        #pragma unroll
        for (int i = 0; i < 4; i++) {
            rv[i] = ((const float4*)(resid + row*ED))[lane + i*32];
            d1 += dot4(v[i], rv[i]);
            d2 += sq4(rv[i]);
            d3 += sq4(v[i]);
        }
        float rxy = warpSumF(d1);
        float ry2 = warpSumF(d2);
        float rx2 = warpSumF(d3);
        float ra = 1.0f + 2.0f*rxy + ry2;
        float rc = 1.0f - rx2;
        float rinv = 1.0f / fmaxf(1.0f + 2.0f*rxy + rx2*ry2, 1e-15f);
        float s3 = 0.0f;
        #pragma unroll
        for (int i = 0; i < 4; i++) {
            VOP4(v[i], (ra*v[i].x + rc*rv[i].x)*rinv, (ra*v[i].y + rc*rv[i].y)*rinv,
                       (ra*v[i].z + rc*rv[i].z)*rinv, (ra*v[i].w + rc*rv[i].w)*rinv);
            s3 += sq4(v[i]);
        }
        float zn = sqrtf(warpSumF(s3) + 1e-30f);
        if (zn > MAXN) { float ps = MAXN / zn;
            #pragma unroll
            for (int i = 0; i < 4; i++) v[i] = scl4(v[i], ps); }
    }
    #pragma unroll
    for (int i = 0; i < 4; i++) ((float4*)(h1out + row*ED))[lane + i*32] = v[i];
    float s0 = 0.0f;
    #pragma unroll
    for (int i = 0; i < 4; i++) s0 += sq4(v[i]);
    float n0 = sqrtf(warpSumF(s0) + 1e-30f);
    float lf = atanhf(fminf(n0, MAXN)) / n0;
    float sm = 0.0f;
    #pragma unroll
    for (int i = 0; i < 4; i++) { v[i] = scl4(v[i], lf); sm += v[i].x + v[i].y + v[i].z + v[i].w; }
    float mu = warpSumF(sm) * (1.0f / ED);
    float vv = 0.0f;
    #pragma unroll
    for (int i = 0; i < 4; i++) {
        float4 d; VOP4(d, v[i].x-mu, v[i].y-mu, v[i].z-mu, v[i].w-mu);
        vv += sq4(d);
    }
    float var = warpSumF(vv) * (1.0f / ED);
    float inv = rsqrtf(var + 1e-5f);
    float s2 = 0.0f;
    #pragma unroll
    for (int i = 0; i < 4; i++) {
        float4 gg = ((const float4*)g)[lane + i*32], bb = ((const float4*)bln)[lane + i*32];
        VOP4(v[i], (v[i].x-mu)*inv*gg.x + bb.x, (v[i].y-mu)*inv*gg.y + bb.y,
                   (v[i].z-mu)*inv*gg.z + bb.z, (v[i].w-mu)*inv*gg.w + bb.w);
        s2 += sq4(v[i]);
    }
    float ny = sqrtf(warpSumF(s2) + 1e-30f);
    float ef = tanhf(ny) / ny;
    #pragma unroll
    for (int i = 0; i < 4; i++) v[i] = scl4(v[i], ef);
    {
        float s3 = 0.0f;
        #pragma unroll
        for (int i = 0; i < 4; i++) s3 += sq4(v[i]);
        float n = sqrtf(warpSumF(s3) + 1e-30f);
        if (n > MAXN) { float ps = MAXN / n;
            #pragma unroll
            for (int i = 0; i < 4; i++) v[i] = scl4(v[i], ps); }
    }
    float s4 = 0.0f;
    #pragma unroll
    for (int i = 0; i < 4; i++) {
        write_split4(v[i], oh + row*ED, ol + row*ED, (lane + i*32)*2);
        s4 += sq4(v[i]);
    }
    float nf = sqrtf(warpSumF(s4) + 1e-30f);
    if (lane == 0) out_norm[row] = nf;
}

// ---------------- fc1 epilogue: warp-per-row over FD=2048 ----------------
__global__ void __launch_bounds__(128) manlin_fc1_w(
    const float* __restrict__ mx, const float* __restrict__ xnb,
    const float* __restrict__ bias,
    __nv_bfloat16* __restrict__ oh, __nv_bfloat16* __restrict__ ol,
    float* __restrict__ out_norm)
{
    const int lane = threadIdx.x & 31;
    const size_t row = blockIdx.x * 4 + (threadIdx.x >> 5);
    const float MAXN = maxnorm();
    const float4* mp = (const float4*)(mx + row * (size_t)FD);
    const float4* bp = (const float4*)bias;
    float4 v[16];
    float ss = 0.0f;
    #pragma unroll
    for (int i = 0; i < 16; i++) { v[i] = mp[lane + i*32]; ss += sq4(v[i]); }
    float mxn = sqrtf(warpSumF(ss) + 1e-30f);
    float xn = xnb[row];
    float s = tanhf(mxn / xn * atanhf(fminf(xn, MAXN))) / mxn;
    float dxy = 0.0f, dx2 = 0.0f;
    #pragma unroll
    for (int i = 0; i < 16; i++) {
        v[i] = scl4(v[i], s);
        dxy += dot4(v[i], bp[lane + i*32]);
        dx2 += sq4(v[i]);
    }
    float xy = warpSumF(dxy);
    float x2 = warpSumF(dx2);
    float y2 = g_b2[4];
    float a = 1.0f + 2.0f*xy + y2;
    float c = 1.0f - x2;
    float invd = 1.0f / fmaxf(1.0f + 2.0f*xy + x2*y2, 1e-15f);
    float zz = 0.0f;
    #pragma unroll
    for (int i = 0; i < 16; i++) {
        float4 bv = bp[lane + i*32];
        VOP4(v[i], (a*v[i].x + c*bv.x)*invd, (a*v[i].y + c*bv.y)*invd,
                   (a*v[i].z + c*bv.z)*invd, (a*v[i].w + c*bv.w)*invd);
        zz += sq4(v[i]);
    }
    {
        float zn = sqrtf(warpSumF(zz) + 1e-30f);
        if (zn > MAXN) { float ps = MAXN / zn;
            #pragma unroll
            for (int i = 0; i < 16; i++) v[i] = scl4(v[i], ps); }
    }
    float s0 = 0.0f;
    #pragma unroll
    for (int i = 0; i < 16; i++) s0 += sq4(v[i]);
    float n = sqrtf(warpSumF(s0) + 1e-30f);
    float lf = atanhf(fminf(n, MAXN)) / n;
    float s1 = 0.0f;
    #pragma unroll
    for (int i = 0; i < 16; i++) {
        VOP4(v[i], fmaxf(lf*v[i].x, 0.0f), fmaxf(lf*v[i].y, 0.0f),
                   fmaxf(lf*v[i].z, 0.0f), fmaxf(lf*v[i].w, 0.0f));
        s1 += sq4(v[i]);
    }
    float nr = sqrtf(warpSumF(s1) + 1e-30f);
    float ef = tanhf(nr) / nr;
    float s2 = 0.0f;
    #pragma unroll
    for (int i = 0; i < 16; i++) { v[i] = scl4(v[i], ef); s2 += sq4(v[i]); }
    {
        float n2 = sqrtf(warpSumF(s2) + 1e-30f);
        if (n2 > MAXN) { float ps = MAXN / n2;
            #pragma unroll
            for (int i = 0; i < 16; i++) v[i] = scl4(v[i], ps); }
    }
    float s5 = 0.0f;
    #pragma unroll
    for (int i = 0; i < 16; i++) {
        write_split4(v[i], oh + row*(size_t)FD, ol + row*(size_t)FD, (lane + i*32)*2);
        s5 += sq4(v[i]);
    }
    float nf = sqrtf(warpSumF(s5) + 1e-30f);
    if (lane == 0) out_norm[row] = nf;
}

// ---------------- final: manlin(W2) + mob_relu + residual -> fp32 out ----------------
__global__ void __launch_bounds__(256) manlin_final_w(
    const float* __restrict__ mx, const float* __restrict__ xnb,
    const float* __restrict__ bias, int b2idx, const float* __restrict__ resid,
    float* __restrict__ outf)
{
    const int lane = threadIdx.x & 31;
    const size_t row = blockIdx.x * 8 + (threadIdx.x >> 5);
    const float MAXN = maxnorm();
    float4 v[4], bvv[4];
    float ss = 0.0f;
    #pragma unroll
    for (int i = 0; i < 4; i++) {
        v[i] = ((const float4*)(mx + row*ED))[lane + i*32];
        bvv[i] = ((const float4*)bias)[lane + i*32];
        ss += sq4(v[i]);
    }
    float mxn = sqrtf(warpSumF(ss) + 1e-30f);
    float xn = xnb[row];
    float s = tanhf(mxn / xn * atanhf(fminf(xn, MAXN))) / mxn;
    float dxy = 0.0f, dx2 = 0.0f;
    #pragma unroll
    for (int i = 0; i < 4; i++) {
        v[i] = scl4(v[i], s);
        dxy += dot4(v[i], bvv[i]);
        dx2 += sq4(v[i]);
    }
    float xy = warpSumF(dxy);
    float x2 = warpSumF(dx2);
    float y2 = g_b2[b2idx];
    float a = 1.0f + 2.0f*xy + y2;
    float c = 1.0f - x2;
    float invd = 1.0f / fmaxf(1.0f + 2.0f*xy + x2*y2, 1e-15f);
    float zz = 0.0f;
    #pragma unroll
    for (int i = 0; i < 4; i++) {
        VOP4(v[i], (a*v[i].x + c*bvv[i].x)*invd, (a*v[i].y + c*bvv[i].y)*invd,
                   (a*v[i].z + c*bvv[i].z)*invd, (a*v[i].w + c*bvv[i].w)*invd);
        zz += sq4(v[i]);
    }
    {
        float zn = sqrtf(warpSumF(zz) + 1e-30f);
        if (zn > MAXN) { float ps = MAXN / zn;
            #pragma unroll
            for (int i = 0; i < 4; i++) v[i] = scl4(v[i], ps); }
    }
    {
        float s0 = 0.0f;
        #pragma unroll
        for (int i = 0; i < 4; i++) s0 += sq4(v[i]);
        float n = sqrtf(warpSumF(s0) + 1e-30f);
        float lf = atanhf(fminf(n, MAXN)) / n;
        float s1 = 0.0f;
        #pragma unroll
        for (int i = 0; i < 4; i++) {
            VOP4(v[i], fmaxf(lf*v[i].x, 0.0f), fmaxf(lf*v[i].y, 0.0f),
                       fmaxf(lf*v[i].z, 0.0f), fmaxf(lf*v[i].w, 0.0f));
            s1 += sq4(v[i]);
        }
        float nr = sqrtf(warpSumF(s1) + 1e-30f);
        float ef = tanhf(nr) / nr;
        float s2 = 0.0f;
        #pragma unroll
        for (int i = 0; i < 4; i++) { v[i] = scl4(v[i], ef); s2 += sq4(v[i]); }
        float n2 = sqrtf(warpSumF(s2) + 1e-30f);
        if (n2 > MAXN) { float ps = MAXN / n2;
            #pragma unroll
            for (int i = 0; i < 4; i++) v[i] = scl4(v[i], ps); }
    }
    {
        float d1 = 0.0f, d2 = 0.0f, d3 = 0.0f;
        float4 rv[4];
        #pragma unroll
        for (int i = 0; i < 4; i++) {
            rv[i] = ((const float4*)(resid + row*ED))[lane + i*32];
            d1 += dot4(v[i], rv[i]);
            d2 += sq4(rv[i]);
            d3 += sq4(v[i]);
        }
        float rxy = warpSumF(d1);
        float ry2 = warpSumF(d2);
        float rx2 = warpSumF(d3);
        float ra = 1.0f + 2.0f*rxy + ry2;
        float rc = 1.0f - rx2;
        float rinv = 1.0f / fmaxf(1.0f + 2.0f*rxy + rx2*ry2, 1e-15f);
        float s3 = 0.0f;
        #pragma unroll
        for (int i = 0; i < 4; i++) {
            VOP4(v[i], (ra*v[i].x + rc*rv[i].x)*rinv, (ra*v[i].y + rc*rv[i].y)*rinv,
                       (ra*v[i].z + rc*rv[i].z)*rinv, (ra*v[i].w + rc*rv[i].w)*rinv);
            s3 += sq4(v[i]);
        }
        float zn = sqrtf(warpSumF(s3) + 1e-30f);
        if (zn > MAXN) { float ps = MAXN / zn;
            #pragma unroll
            for (int i = 0; i < 4; i++) v[i] = scl4(v[i], ps); }
    }
    #pragma unroll
    for (int i = 0; i < 4; i++) ((float4*)(outf + row*ED))[lane + i*32] = v[i];
}

// ---------------- MMA helpers ----------------
__device__ __forceinline__ void ldsm_x4(uint32_t &r0, uint32_t &r1, uint32_t &r2, uint32_t &r3, uint32_t addr) {
    asm volatile("ldmatrix.sync.aligned.m8n8.x4.shared.b16 {%0,%1,%2,%3}, [%4];"
                 : "=r"(r0), "=r"(r1), "=r"(r2), "=r"(r3) : "r"(addr));
}
__device__ __forceinline__ void ldsm_x4t(uint32_t &r0, uint32_t &r1, uint32_t &r2, uint32_t &r3, uint32_t addr) {
    asm volatile("ldmatrix.sync.aligned.m8n8.x4.trans.shared.b16 {%0,%1,%2,%3}, [%4];"
                 : "=r"(r0), "=r"(r1), "=r"(r2), "=r"(r3) : "r"(addr));
}
__device__ __forceinline__ void mma16816(float* c, const uint32_t* a, const uint32_t* b) {
    asm volatile("mma.sync.aligned.m16n8k16.row.col.f32.bf16.bf16.f32 "
                 "{%0,%1,%2,%3}, {%4,%5,%6,%7}, {%8,%9}, {%0,%1,%2,%3};"
                 : "+f"(c[0]), "+f"(c[1]), "+f"(c[2]), "+f"(c[3])
                 : "r"(a[0]), "r"(a[1]), "r"(a[2]), "r"(a[3]), "r"(b[0]), "r"(b[1]));
}
#define CP_ASYNC16(dst, src) asm volatile("cp.async.cg.shared.global [%0], [%1], 16;" :: "r"(dst), "l"(src))

// ---------------- tensor-core attention: Q/K/V in 96KB smem, forced 2 CTAs/SM ----------------
#define ATT_SMEM 98304
__global__ void __launch_bounds__(256, 2) attn_mma(
    const __nv_bfloat16* __restrict__ qh_g, const __nv_bfloat16* __restrict__ ql_g,
    float* __restrict__ o)
{
    extern __shared__ __nv_bfloat16 smbuf[];
    uint32_t smb = (uint32_t)__cvta_generic_to_shared(smbuf);
    const int tid = threadIdx.x;
    const int lane = tid & 31, w = tid >> 5;
    const int bh = blockIdx.x, b = bh >> 3, h = bh & 7;

    #pragma unroll
    for (int it = 0; it < 24; it++) {
        int idx = tid + (it << 8);
        int tensor = idx >> 10;
        int cid = idx & 1023;
        int r = cid >> 3, c = cid & 7;
        uint32_t dst = smb + tensor*16384 + r*128 + ((c ^ (r & 7)) << 4);
        const __nv_bfloat16* P = (tensor & 1) ? ql_g : qh_g;
        const __nv_bfloat16* src = P + ((size_t)r*BB + b)*QKVW + (size_t)(tensor>>1)*512 + h*HD + c*8;
        CP_ASYNC16(dst, src);
    }
    asm volatile("cp.async.commit_group;");
    asm volatile("cp.async.wait_group 0;");
    __syncthreads();

    const int quad = lane >> 3, r8 = lane & 7;

    float sc[16][4];
    #pragma unroll
    for (int n = 0; n < 16; n++)
        #pragma unroll
        for (int e = 0; e < 4; e++) sc[n][e] = 0.0f;

    #pragma unroll
    for (int kk = 0; kk < 4; kk++) {
        uint32_t qh_[4], ql_[4];
        int arow = w*16 + (quad & 1)*8 + r8;
        int achk = kk*2 + (quad >> 1);
        uint32_t aoff = (uint32_t)(arow*128 + ((achk ^ (arow & 7)) << 4));
        ldsm_x4(qh_[0], qh_[1], qh_[2], qh_[3], smb + aoff);
        ldsm_x4(ql_[0], ql_[1], ql_[2], ql_[3], smb + 16384 + aoff);
        #pragma unroll
        for (int nn = 0; nn < 8; nn++) {
            int krow = nn*16 + (quad >> 1)*8 + r8;
            int kchk = kk*2 + (quad & 1);
            uint32_t koff = (uint32_t)(krow*128 + ((kchk ^ (krow & 7)) << 4));
            uint32_t kh0[2], kh1[2], kl0[2], kl1[2];
            { uint32_t a0,a1,a2,a3; ldsm_x4(a0,a1,a2,a3, smb + 32768 + koff);
              kh0[0]=a0; kh0[1]=a1; kh1[0]=a2; kh1[1]=a3; }
            { uint32_t a0,a1,a2,a3; ldsm_x4(a0,a1,a2,a3, smb + 49152 + koff);
              kl0[0]=a0; kl0[1]=a1; kl1[0]=a2; kl1[1]=a3; }
            mma16816(sc[2*nn],   qh_, kh0);
            mma16816(sc[2*nn],   qh_, kl0);
            mma16816(sc[2*nn],   ql_, kh0);
            mma16816(sc[2*nn+1], qh_, kh1);
            mma16816(sc[2*nn+1], qh_, kl1);
            mma16816(sc[2*nn+1], ql_, kh1);
        }
    }

    float m0 = -1e30f, m1 = -1e30f;
    #pragma unroll
    for (int n = 0; n < 16; n++) {
        m0 = fmaxf(m0, fmaxf(sc[n][0], sc[n][1]));
        m1 = fmaxf(m1, fmaxf(sc[n][2], sc[n][3]));
    }
    m0 = fmaxf(m0, __shfl_xor_sync(0xffffffffu, m0, 1));
    m0 = fmaxf(m0, __shfl_xor_sync(0xffffffffu, m0, 2));
    m1 = fmaxf(m1, __shfl_xor_sync(0xffffffffu, m1, 1));
    m1 = fmaxf(m1, __shfl_xor_sync(0xffffffffu, m1, 2));
    float l0 = 0.0f, l1 = 0.0f;
    #pragma unroll
    for (int n = 0; n < 16; n++) {
        sc[n][0] = fexp((sc[n][0] - m0) * 0.125f); l0 += sc[n][0];
        sc[n][1] = fexp((sc[n][1] - m0) * 0.125f); l0 += sc[n][1];
        sc[n][2] = fexp((sc[n][2] - m1) * 0.125f); l1 += sc[n][2];
        sc[n][3] = fexp((sc[n][3] - m1) * 0.125f); l1 += sc[n][3];
    }
    l0 += __shfl_xor_sync(0xffffffffu, l0, 1);
    l0 += __shfl_xor_sync(0xffffffffu, l0, 2);
    l1 += __shfl_xor_sync(0xffffffffu, l1, 1);
    l1 += __shfl_xor_sync(0xffffffffu, l1, 2);
    float inv0 = 1.0f / l0, inv1 = 1.0f / l1;

    float oa[8][4];
    #pragma unroll
    for (int n = 0; n < 8; n++)
        #pragma unroll
        for (int e = 0; e < 4; e++) oa[n][e] = 0.0f;

    #pragma unroll
    for (int kt = 0; kt < 8; kt++) {
        uint32_t ph[4], pl[4];
        #pragma unroll
        for (int half = 0; half < 2; half++) {
            int n2 = 2*kt + half;
            float p0 = sc[n2][0], p1 = sc[n2][1], p2 = sc[n2][2], p3 = sc[n2][3];
            __nv_bfloat16 b0 = __float2bfloat16(p0), b1 = __float2bfloat16(p1);
            __nv_bfloat16 b2 = __float2bfloat16(p2), b3 = __float2bfloat16(p3);
            ph[half*2+0] = pack_bf2(p0, p1);
            ph[half*2+1] = pack_bf2(p2, p3);
            pl[half*2+0] = pack_bf2(p0 - __bfloat162float(b0), p1 - __bfloat162float(b1));
            pl[half*2+1] = pack_bf2(p2 - __bfloat162float(b2), p3 - __bfloat162float(b3));
        }
        #pragma unroll
        for (int nn = 0; nn < 4; nn++) {
            int vrow = kt*16 + (quad & 1)*8 + r8;
            int vchk = 2*nn + (quad >> 1);
            uint32_t voff = (uint32_t)(vrow*128 + ((vchk ^ (vrow & 7)) << 4));
            uint32_t vh0[2], vh1[2], vl0[2], vl1[2];
            { uint32_t a0,a1,a2,a3; ldsm_x4t(a0,a1,a2,a3, smb + 65536 + voff);
              vh0[0]=a0; vh0[1]=a1; vh1[0]=a2; vh1[1]=a3; }
            { uint32_t a0,a1,a2,a3; ldsm_x4t(a0,a1,a2,a3, smb + 81920 + voff);
              vl0[0]=a0; vl0[1]=a1; vl1[0]=a2; vl1[1]=a3; }
            mma16816(oa[2*nn],   ph, vh0);
            mma16816(oa[2*nn],   ph, vl0);
            mma16816(oa[2*nn],   pl, vh0);
            mma16816(oa[2*nn+1], ph, vh1);
            mma16816(oa[2*nn+1], ph, vl1);
            mma16816(oa[2*nn+1], pl, vh1);
        }
    }

    int g = lane >> 2, t2 = (lane & 3) * 2;
    int t0 = w*16 + g;
    #pragma unroll
    for (int n = 0; n < 8; n++) {
        size_t base0 = ((size_t)t0*BB + b)*ED + (size_t)h*HD + n*8 + t2;
        size_t base1 = ((size_t)(t0+8)*BB + b)*ED + (size_t)h*HD + n*8 + t2;
        *(float2*)(o + base0) = make_float2(oa[n][0]*inv0, oa[n][1]*inv0);
        *(float2*)(o + base1) = make_float2(oa[n][2]*inv1, oa[n][3]*inv1);
    }
}

// ================= bf16x3 HMMA GEMM (operand-ordered loads: B-hi, A-hi, B-lo, A-lo) =================
#define BM 128
#define BN 128
#define BK 32
#define TEN_B   8192
#define STAGE_B (4*TEN_B)
#define GEMM_SMEM (3*STAGE_B)

__device__ __forceinline__ uint32_t saddr(int r, int colElem) {
    return (uint32_t)(r*64 + ((((colElem >> 3) ^ ((r >> 1) & 3))) << 4));
}

__global__ void __launch_bounds__(256, 2) gemm_bf16x3(
    const __nv_bfloat16* __restrict__ Ah, const __nv_bfloat16* __restrict__ Al,
    const __nv_bfloat16* __restrict__ Wh, const __nv_bfloat16* __restrict__ Wl,
    float* __restrict__ C, int M, int N, int K)
{
    extern __shared__ __nv_bfloat16 smbuf[];
    const int tid = threadIdx.x;
    const int lane = tid & 31, w = tid >> 5;
    const int wm = w & 1, wn = w >> 1;
    const int rowBase = blockIdx.y * BM;
    const int colBase = blockIdx.x * BN;
    uint32_t smbase = (uint32_t)__cvta_generic_to_shared(smbuf);

    float acc[4][4][4];
    #pragma unroll
    for (int i = 0; i < 4; i++)
        #pragma unroll
        for (int j = 0; j < 4; j++)
            #pragma unroll
            for (int e = 0; e < 4; e++) acc[i][j][e] = 0.0f;

    auto load_stage = [&](int st, int k0) {
        uint32_t base = smbase + st * STAGE_B;
        #pragma unroll
        for (int it = 0; it < 8; it++) {
            int idx = tid + (it << 8);
            int tensor = idx >> 9;
            int cid = idx & 511;
            int r = cid >> 2, c = cid & 3;
            uint32_t dst = base + tensor * TEN_B
                         + (uint32_t)(r*64 + ((c ^ ((r >> 1) & 3)) << 4));
            const __nv_bfloat16* src;
            if (tensor == 0)      src = Ah + (size_t)(rowBase + r) * K + k0 + c * 8;
            else if (tensor == 1) src = Al + (size_t)(rowBase + r) * K + k0 + c * 8;
            else if (tensor == 2) src = Wh + (size_t)(colBase + r) * K + k0 + c * 8;
            else                  src = Wl + (size_t)(colBase + r) * K + k0 + c * 8;
            CP_ASYNC16(dst, src);
        }
        asm volatile("cp.async.commit_group;");
    };

    auto compute_stage = [&](int st) {
        uint32_t base = smbase + st * STAGE_B;
        uint32_t aH = base;
        uint32_t aL = base + 1*TEN_B;
        uint32_t wH = base + 2*TEN_B;
        uint32_t wL = base + 3*TEN_B;
        const int quad = lane >> 3, r8 = lane & 7;
        #pragma unroll
        for (int kk = 0; kk < BK; kk += 16) {
            uint32_t ah[4][4], al[4][4], bh[4][2], bl[4][2];
            // 1) pass-1 operands first: B-hi then A-hi
            #pragma unroll
            for (int jj = 0; jj < 2; jj++) {
                int nr = wn*32 + jj*16 + (quad >> 1)*8 + r8;
                int kc = kk + (quad & 1)*8;
                uint32_t off = saddr(nr, kc);
                uint32_t a0,a1,a2,a3;
                ldsm_x4(a0,a1,a2,a3, wH + off);
                bh[2*jj][0]=a0; bh[2*jj][1]=a1; bh[2*jj+1][0]=a2; bh[2*jj+1][1]=a3;
            }
            #pragma unroll
            for (int i = 0; i < 4; i++) {
                int row = wm*64 + i*16 + (quad & 1)*8 + r8;
                int col = kk + (quad >> 1)*8;
                uint32_t off = saddr(row, col);
                ldsm_x4(ah[i][0], ah[i][1], ah[i][2], ah[i][3], aH + off);
            }
            // 2) later-pass operands issued next; their latency is covered by pass-1 MMAs
            #pragma unroll
            for (int jj = 0; jj < 2; jj++) {
                int nr = wn*32 + jj*16 + (quad >> 1)*8 + r8;
                int kc = kk + (quad & 1)*8;
                uint32_t off = saddr(nr, kc);
                uint32_t a0,a1,a2,a3;
                ldsm_x4(a0,a1,a2,a3, wL + off);
                bl[2*jj][0]=a0; bl[2*jj][1]=a1; bl[2*jj+1][0]=a2; bl[2*jj+1][1]=a3;
            }
            #pragma unroll
            for (int i = 0; i < 4; i++) {
                int row = wm*64 + i*16 + (quad & 1)*8 + r8;
                int col = kk + (quad >> 1)*8;
                uint32_t off = saddr(row, col);
                ldsm_x4(al[i][0], al[i][1], al[i][2], al[i][3], aL + off);
            }
            // pass 1: ah x bh  (operands were first in flight)
            #pragma unroll
            for (int i = 0; i < 4; i++)
                #pragma unroll
                for (int j = 0; j < 4; j++) mma16816(acc[i][j], ah[i], bh[j]);
            // pass 2: ah x bl
            #pragma unroll
            for (int i = 0; i < 4; i++)
                #pragma unroll
                for (int j = 0; j < 4; j++) mma16816(acc[i][j], ah[i], bl[j]);
            // pass 3: al x bh
            #pragma unroll
            for (int i = 0; i < 4; i++)
                #pragma unroll
                for (int j = 0; j < 4; j++) mma16816(acc[i][j], al[i], bh[j]);
        }
    };

    const int nkb = K / BK;
    load_stage(0, 0);
    load_stage(1, BK);
    for (int kb = 0; kb < nkb; kb++) {
        if (kb == nkb - 1) { asm volatile("cp.async.wait_group 0;"); }
        else               { asm volatile("cp.async.wait_group 1;"); }
        __syncthreads();
        if (kb + 2 < nkb) load_stage((kb + 2) % 3, (kb + 2) * BK);
        compute_stage(kb % 3);
    }

    const int g = lane >> 2, tg = lane & 3;
    #pragma unroll
    for (int i = 0; i < 4; i++) {
        int row = rowBase + wm*64 + i*16 + g;
        #pragma unroll
        for (int j = 0; j < 4; j++) {
            int col = colBase + wn*32 + j*8 + tg*2;
            *(float2*)(C + (size_t)row * N + col)       = make_float2(acc[i][j][0], acc[i][j][1]);
            *(float2*)(C + (size_t)(row + 8) * N + col) = make_float2(acc[i][j][2], acc[i][j][3]);
        }
    }
}

// ---------------- launch ----------------
extern "C" void kernel_launch(void* const* d_in, const int* in_sizes, int n_in,
                              void* d_out, int out_size)
{
    const float* x    = (const float*)d_in[0];
    const float* l1g  = (const float*)d_in[1];
    const float* l1b  = (const float*)d_in[2];
    const float* l2g  = (const float*)d_in[3];
    const float* l2b  = (const float*)d_in[4];
    const float* Wq   = (const float*)d_in[5];
    const float* bq   = (const float*)d_in[6];
    const float* Wk   = (const float*)d_in[7];
    const float* bk   = (const float*)d_in[8];
    const float* Wv   = (const float*)d_in[9];
    const float* bv   = (const float*)d_in[10];
    const float* Wo   = (const float*)d_in[11];
    const float* bo   = (const float*)d_in[12];
    const float* W1   = (const float*)d_in[13];
    const float* b1   = (const float*)d_in[14];
    const float* W2   = (const float*)d_in[15];
    const float* b2   = (const float*)d_in[16];
    float* out = (float*)d_out;

    float *qkv, *ob, *h1, *big, *n0, *no, *nh2, *nh3, *bsq;
    __nv_bfloat16 *xh, *xl, *wh, *wl;
    cudaGetSymbolAddress((void**)&qkv, g_qkv);
    cudaGetSymbolAddress((void**)&ob,  g_o);
    cudaGetSymbolAddress((void**)&h1,  g_h1);
    cudaGetSymbolAddress((void**)&big, g_big);
    cudaGetSymbolAddress((void**)&xh,  g_xh);
    cudaGetSymbolAddress((void**)&xl,  g_xl);
    cudaGetSymbolAddress((void**)&wh,  g_wh);
    cudaGetSymbolAddress((void**)&wl,  g_wl);
    cudaGetSymbolAddress((void**)&n0,  g_n0);
    cudaGetSymbolAddress((void**)&no,  g_no);
    cudaGetSymbolAddress((void**)&nh2, g_nh2);
    cudaGetSymbolAddress((void**)&nh3, g_nh3);
    cudaGetSymbolAddress((void**)&bsq, g_b2);

    cudaFuncSetAttribute(gemm_bf16x3, cudaFuncAttributeMaxDynamicSharedMemorySize, GEMM_SMEM);
    cudaFuncSetAttribute(attn_mma, cudaFuncAttributeMaxDynamicSharedMemorySize, ATT_SMEM);

    prep_kernel<<<PREP_BLOCKS, 256>>>(Wq, Wk, Wv, Wo, W1, W2,
                                      bq, bk, bv, bo, b1, b2,
                                      x, l1g, l1b, wh, wl, xh, xl, n0, bsq);

    gemm_bf16x3<<<dim3(QKVW/BN, NR/BM), 256, GEMM_SMEM>>>(xh, xl, wh + WQ0, wl + WQ0, qkv, NR, QKVW, ED);
    manlin_qkv_w<<<dim3(NR/8, 3), 256>>>(qkv, n0, bq, bk, bv, xh, xl);

    attn_mma<<<BB * NH, 256, ATT_SMEM>>>(xh, xl, ob);
    expmap_w<<<NR/8, 256>>>(ob, xh, xl, no);

    gemm_bf16x3<<<dim3(ED/BN, NR/BM), 256, GEMM_SMEM>>>(xh, xl, wh + WO0, wl + WO0, big, NR, ED, ED);
    manlin_ln_w<<<NR/8, 256>>>(big, no, bo, 3, x, h1, l2g, l2b, xh, xl, nh2);

    gemm_bf16x3<<<dim3(FD/BN, NR/BM), 256, GEMM_SMEM>>>(xh, xl, wh + W10, wl + W10, big, NR, FD, ED);
    manlin_fc1_w<<<NR/4, 128>>>(big, nh2, b1, xh, xl, nh3);

    gemm_bf16x3<<<dim3(ED/BN, NR/BM), 256, GEMM_SMEM>>>(xh, xl, wh + W20, wl + W20, qkv, NR, ED, FD);
    manlin_final_w<<<NR/8, 256>>>(qkv, nh3, b2, 5, h1, out);
}

// round 15
// speedup vs baseline: 1.0221x; 1.0221x over previous
#include <cuda_runtime.h>
#include <cuda_bf16.h>
#include <math.h>
#include <stdint.h>

// ---------------- problem constants ----------------
#define SEQ 128
#define BB  256
#define ED  512
#define FD  2048
#define NH  8
#define HD  64
#define NR  (SEQ*BB)   // 32768 rows
#define QKVW 1536      // fused qkv row width

static __device__ __forceinline__ float maxnorm() { return (float)(1.0 - 1e-5); }

// ---------------- scratch ----------------
__device__ float g_qkv[(size_t)NR*QKVW];
__device__ float g_o  [(size_t)NR*ED];
__device__ float g_h1 [(size_t)NR*ED];
__device__ float g_big[(size_t)NR*FD];
__device__ __nv_bfloat16 g_xh[(size_t)NR*FD];
__device__ __nv_bfloat16 g_xl[(size_t)NR*FD];
__device__ __nv_bfloat16 g_wh[(size_t)3*1024*1024];
__device__ __nv_bfloat16 g_wl[(size_t)3*1024*1024];
__device__ float g_n0 [NR];
__device__ float g_no [NR];
__device__ float g_nh2[NR];
__device__ float g_nh3[NR];
__device__ float g_b2 [8];

#define WQ0 0
#define WK0 262144
#define WV0 524288
#define WO0 786432
#define W10 1048576
#define W20 2097152

// ---------------- reductions ----------------
template <int T>
__device__ __forceinline__ float blockSumF(float v) {
    __shared__ float sh[T / 32];
    #pragma unroll
    for (int o = 16; o > 0; o >>= 1) v += __shfl_xor_sync(0xffffffffu, v, o);
    int lane = threadIdx.x & 31, w = threadIdx.x >> 5;
    if (lane == 0) sh[w] = v;
    __syncthreads();
    if (threadIdx.x < 32) {
        float t = (threadIdx.x < T / 32) ? sh[threadIdx.x] : 0.0f;
        #pragma unroll
        for (int o = 16; o > 0; o >>= 1) t += __shfl_xor_sync(0xffffffffu, t, o);
        if (threadIdx.x == 0) sh[0] = t;
    }
    __syncthreads();
    float r = sh[0];
    __syncthreads();
    return r;
}
__device__ __forceinline__ float warpSumF(float v) {
    #pragma unroll
    for (int o = 16; o > 0; o >>= 1) v += __shfl_xor_sync(0xffffffffu, v, o);
    return v;
}

__device__ __forceinline__ void split1(float x, __nv_bfloat16 &h, __nv_bfloat16 &l) {
    h = __float2bfloat16(x);
    l = __float2bfloat16(x - __bfloat162float(h));
}
__device__ __forceinline__ uint32_t pack_bf2(float a, float b) {
    __nv_bfloat162 t(__float2bfloat16(a), __float2bfloat16(b));
    return *(uint32_t*)&t;
}

// FMA-pipe exp (no MUFU)
__device__ __forceinline__ float fexp(float x) {
    float y = x * 1.4426950408889634f;
    y = fmaxf(y, -126.0f);
    float fl = floorf(y);
    float f = y - fl;
    float p = 1.5252734e-5f;
    p = fmaf(p, f, 1.5403530e-4f);
    p = fmaf(p, f, 1.3333558e-3f);
    p = fmaf(p, f, 9.6181291e-3f);
    p = fmaf(p, f, 5.5504109e-2f);
    p = fmaf(p, f, 2.4022651e-1f);
    p = fmaf(p, f, 6.9314718e-1f);
    p = fmaf(p, f, 1.0f);
    return __int_as_float(__float_as_int(p) + (((int)fl) << 23));
}

// vector helpers
#define VOP4(dst, ex, ey, ez, ew) do { dst.x=(ex); dst.y=(ey); dst.z=(ez); dst.w=(ew); } while(0)
__device__ __forceinline__ float dot4(float4 a, float4 b) { return a.x*b.x + a.y*b.y + a.z*b.z + a.w*b.w; }
__device__ __forceinline__ float sq4(float4 a) { return dot4(a, a); }
__device__ __forceinline__ float4 scl4(float4 a, float s) { float4 r; VOP4(r, a.x*s, a.y*s, a.z*s, a.w*s); return r; }

__device__ __forceinline__ void write_split4(float4 v, __nv_bfloat16* oh, __nv_bfloat16* ol, int idx2) {
    __nv_bfloat16 h0,l0,h1,l1,h2,l2,h3,l3;
    split1(v.x,h0,l0); split1(v.y,h1,l1); split1(v.z,h2,l2); split1(v.w,h3,l3);
    ((__nv_bfloat162*)oh)[idx2]   = __nv_bfloat162(h0,h1);
    ((__nv_bfloat162*)oh)[idx2+1] = __nv_bfloat162(h2,h3);
    ((__nv_bfloat162*)ol)[idx2]   = __nv_bfloat162(l0,l1);
    ((__nv_bfloat162*)ol)[idx2+1] = __nv_bfloat162(l2,l3);
}

// ================= fused prep: weight splits + bias norms + ln1 (one launch) =================
#define PREP_BLOCKS (3072 + 6 + NR/8)
__global__ void __launch_bounds__(256) prep_kernel(
    const float* Wq, const float* Wk, const float* Wv,
    const float* Wo, const float* W1, const float* W2,
    const float* bq, const float* bk, const float* bv,
    const float* bo, const float* b1, const float* b2,
    const float* __restrict__ x, const float* __restrict__ l1g, const float* __restrict__ l1b,
    __nv_bfloat16* __restrict__ wh, __nv_bfloat16* __restrict__ wl,
    __nv_bfloat16* __restrict__ xh, __nv_bfloat16* __restrict__ xl,
    float* __restrict__ n0out, float* __restrict__ bsq)
{
    const int bid = blockIdx.x;
    if (bid < 3072) {
        const float* src; size_t off; int sub;
        if (bid < 1024) {
            sub = bid & 255;
            switch (bid >> 8) {
                case 0: src = Wq; off = WQ0; break;
                case 1: src = Wk; off = WK0; break;
                case 2: src = Wv; off = WV0; break;
                default: src = Wo; off = WO0; break;
            }
        } else if (bid < 2048) { src = W1; off = W10; sub = bid - 1024; }
        else                   { src = W2; off = W20; sub = bid - 2048; }
        int i = sub * 256 + threadIdx.x;
        float4 v = ((const float4*)src)[i];
        __nv_bfloat16 h0,l0,h1,l1,h2,l2,h3,l3;
        split1(v.x, h0, l0); split1(v.y, h1, l1);
        split1(v.z, h2, l2); split1(v.w, h3, l3);
        __nv_bfloat162* hp = (__nv_bfloat162*)(wh + off);
        __nv_bfloat162* lp = (__nv_bfloat162*)(wl + off);
        hp[i*2]   = __nv_bfloat162(h0, h1);
        hp[i*2+1] = __nv_bfloat162(h2, h3);
        lp[i*2]   = __nv_bfloat162(l0, l1);
        lp[i*2+1] = __nv_bfloat162(l2, l3);
        return;
    }
    if (bid < 3078) {
        int task = bid - 3072;
        const float* p; int n;
        switch (task) {
            case 0: p = bq; n = ED; break;
            case 1: p = bk; n = ED; break;
            case 2: p = bv; n = ED; break;
            case 3: p = bo; n = ED; break;
            case 4: p = b1; n = FD; break;
            default: p = b2; n = ED; break;
        }
        float s = 0.0f;
        for (int i = threadIdx.x; i < n; i += 256) { float xx = p[i]; s += xx * xx; }
        s = blockSumF<256>(s);
        if (threadIdx.x == 0) bsq[task] = s;
        return;
    }
    // ln1 warp-per-row
    const int lane = threadIdx.x & 31;
    const size_t row = (size_t)(bid - 3078) * 8 + (threadIdx.x >> 5);
    const float MAXN = maxnorm();
    const float4* xp = (const float4*)(x + row * ED);
    float4 v[4];
    float ss = 0.0f;
    #pragma unroll
    for (int i = 0; i < 4; i++) { v[i] = xp[lane + i*32]; ss += sq4(v[i]); }
    float nn0 = sqrtf(warpSumF(ss) + 1e-30f);
    float lf = atanhf(fminf(nn0, MAXN)) / nn0;
    float sm = 0.0f;
    #pragma unroll
    for (int i = 0; i < 4; i++) { v[i] = scl4(v[i], lf); sm += v[i].x + v[i].y + v[i].z + v[i].w; }
    float mu = warpSumF(sm) * (1.0f / ED);
    float vv = 0.0f;
    #pragma unroll
    for (int i = 0; i < 4; i++) {
        float4 d; VOP4(d, v[i].x-mu, v[i].y-mu, v[i].z-mu, v[i].w-mu);
        vv += sq4(d);
    }
    float var = warpSumF(vv) * (1.0f / ED);
    float inv = rsqrtf(var + 1e-5f);
    float s2 = 0.0f;
    #pragma unroll
    for (int i = 0; i < 4; i++) {
        float4 gg = ((const float4*)l1g)[lane + i*32], bb = ((const float4*)l1b)[lane + i*32];
        VOP4(v[i], (v[i].x-mu)*inv*gg.x + bb.x, (v[i].y-mu)*inv*gg.y + bb.y,
                   (v[i].z-mu)*inv*gg.z + bb.z, (v[i].w-mu)*inv*gg.w + bb.w);
        s2 += sq4(v[i]);
    }
    float ny = sqrtf(warpSumF(s2) + 1e-30f);
    float ef = tanhf(ny) / ny;
    float s4 = 0.0f;
    #pragma unroll
    for (int i = 0; i < 4; i++) {
        v[i] = scl4(v[i], ef);
        write_split4(v[i], xh + row*ED, xl + row*ED, (lane + i*32)*2);
        s4 += sq4(v[i]);
    }
    float nf = sqrtf(warpSumF(s4) + 1e-30f);
    if (lane == 0) n0out[row] = nf;
}

// ================= warp-per-row kernels =================

// ---------------- expmap0 ----------------
__global__ void __launch_bounds__(256) expmap_w(
    const float* __restrict__ x, __nv_bfloat16* __restrict__ oh, __nv_bfloat16* __restrict__ ol,
    float* __restrict__ out_norm)
{
    const int lane = threadIdx.x & 31;
    const size_t row = blockIdx.x * 8 + (threadIdx.x >> 5);
    const float4* xp = (const float4*)(x + row * ED);
    float4 v[4];
    float ss = 0.0f;
    #pragma unroll
    for (int i = 0; i < 4; i++) { v[i] = xp[lane + i*32]; ss += sq4(v[i]); }
    float n = sqrtf(warpSumF(ss) + 1e-30f);
    float ef = tanhf(n) / n;
    float s2 = 0.0f;
    #pragma unroll
    for (int i = 0; i < 4; i++) {
        v[i] = scl4(v[i], ef);
        write_split4(v[i], oh + row*ED, ol + row*ED, (lane + i*32)*2);
        s2 += sq4(v[i]);
    }
    float nf = sqrtf(warpSumF(s2) + 1e-30f);
    if (lane == 0) out_norm[row] = nf;
}

// ---------------- q/k/v manifold epilogue ----------------
__global__ void __launch_bounds__(256) manlin_qkv_w(
    const float* __restrict__ qkvf, const float* __restrict__ xnb,
    const float* __restrict__ bq, const float* __restrict__ bk, const float* __restrict__ bv,
    __nv_bfloat16* __restrict__ oh, __nv_bfloat16* __restrict__ ol)
{
    const int lane = threadIdx.x & 31;
    const size_t row = blockIdx.x * 8 + (threadIdx.x >> 5);
    const int seg = blockIdx.y;
    const float MAXN = maxnorm();
    const float* bias = (seg == 0) ? bq : (seg == 1) ? bk : bv;
    const float4* base = (const float4*)(qkvf + row * (size_t)QKVW + seg * 512);
    float4 v[4], bvv[4];
    float ss = 0.0f;
    #pragma unroll
    for (int i = 0; i < 4; i++) {
        v[i] = base[lane + i*32];
        bvv[i] = ((const float4*)bias)[lane + i*32];
        ss += sq4(v[i]);
    }
    float mxn = sqrtf(warpSumF(ss) + 1e-30f);
    float xn = xnb[row];
    float s = tanhf(mxn / xn * atanhf(fminf(xn, MAXN))) / mxn;
    float dxy = 0.0f, dx2 = 0.0f;
    #pragma unroll
    for (int i = 0; i < 4; i++) {
        v[i] = scl4(v[i], s);
        dxy += dot4(v[i], bvv[i]);
        dx2 += sq4(v[i]);
    }
    float xy = warpSumF(dxy);
    float x2 = warpSumF(dx2);
    float y2 = g_b2[seg];
    float a = 1.0f + 2.0f*xy + y2;
    float c = 1.0f - x2;
    float invd = 1.0f / fmaxf(1.0f + 2.0f*xy + x2*y2, 1e-15f);
    float zz = 0.0f;
    #pragma unroll
    for (int i = 0; i < 4; i++) {
        VOP4(v[i], (a*v[i].x + c*bvv[i].x)*invd, (a*v[i].y + c*bvv[i].y)*invd,
                   (a*v[i].z + c*bvv[i].z)*invd, (a*v[i].w + c*bvv[i].w)*invd);
        zz += sq4(v[i]);
    }
    float zn = sqrtf(warpSumF(zz) + 1e-30f);
    if (zn > MAXN) {
        float ps = MAXN / zn;
        #pragma unroll
        for (int i = 0; i < 4; i++) v[i] = scl4(v[i], ps);
    }
    float s0 = 0.0f;
    #pragma unroll
    for (int i = 0; i < 4; i++) s0 += sq4(v[i]);
    float n = sqrtf(warpSumF(s0) + 1e-30f);
    float lf = atanhf(fminf(n, MAXN)) / n;
    size_t ob = row * (size_t)QKVW + seg * 512;
    #pragma unroll
    for (int i = 0; i < 4; i++) {
        v[i] = scl4(v[i], lf);
        write_split4(v[i], oh + ob, ol + ob, (lane + i*32)*2);
    }
}

// ---------------- fused: manlin(Wo)+residual -> ln2 -> splits ----------------
__global__ void __launch_bounds__(256) manlin_ln_w(
    const float* __restrict__ mx, const float* __restrict__ xnb,
    const float* __restrict__ bias, int b2idx, const float* __restrict__ resid,
    float* __restrict__ h1out,
    const float* __restrict__ g, const float* __restrict__ bln,
    __nv_bfloat16* __restrict__ oh, __nv_bfloat16* __restrict__ ol,
    float* __restrict__ out_norm)
{
    const int lane = threadIdx.x & 31;
    const size_t row = blockIdx.x * 8 + (threadIdx.x >> 5);
    const float MAXN = maxnorm();
    float4 v[4], bvv[4];
    float ss = 0.0f;
    #pragma unroll
    for (int i = 0; i < 4; i++) {
        v[i] = ((const float4*)(mx + row*ED))[lane + i*32];
        bvv[i] = ((const float4*)bias)[lane + i*32];
        ss += sq4(v[i]);
    }
    float mxn = sqrtf(warpSumF(ss) + 1e-30f);
    float xn = xnb[row];
    float s = tanhf(mxn / xn * atanhf(fminf(xn, MAXN))) / mxn;
    float dxy = 0.0f, dx2 = 0.0f;
    #pragma unroll
    for (int i = 0; i < 4; i++) {
        v[i] = scl4(v[i], s);
        dxy += dot4(v[i], bvv[i]);
        dx2 += sq4(v[i]);
    }
    float xy = warpSumF(dxy);
    float x2 = warpSumF(dx2);
    float y2 = g_b2[b2idx];
    float a = 1.0f + 2.0f*xy + y2;
    float c = 1.0f - x2;
    float invd = 1.0f / fmaxf(1.0f + 2.0f*xy + x2*y2, 1e-15f);
    float zz = 0.0f;
    #pragma unroll
    for (int i = 0; i < 4; i++) {
        VOP4(v[i], (a*v[i].x + c*bvv[i].x)*invd, (a*v[i].y + c*bvv[i].y)*invd,
                   (a*v[i].z + c*bvv[i].z)*invd, (a*v[i].w + c*bvv[i].w)*invd);
        zz += sq4(v[i]);
    }
    {
        float zn = sqrtf(warpSumF(zz) + 1e-30f);
        if (zn > MAXN) { float ps = MAXN / zn;
            #pragma unroll
            for (int i = 0; i < 4; i++) v[i] = scl4(v[i], ps); }
    }
    {
        float d1 = 0.0f, d2 = 0.0f, d3 = 0.0f;
        float4 rv[4];
        #pragma unroll
        for (int i = 0; i < 4; i++) {
            rv[i] = ((const float4*)(resid + row*ED))[lane + i*32];
            d1 += dot4(v[i], rv[i]);
            d2 += sq4(rv[i]);
            d3 += sq4(v[i]);
        }
        float rxy = warpSumF(d1);
        float ry2 = warpSumF(d2);
        float rx2 = warpSumF(d3);
        float ra = 1.0f + 2.0f*rxy + ry2;
        float rc = 1.0f - rx2;
        float rinv = 1.0f / fmaxf(1.0f + 2.0f*rxy + rx2*ry2, 1e-15f);
        float s3 = 0.0f;
        #pragma unroll
        for (int i = 0; i < 4; i++) {
            VOP4(v[i], (ra*v[i].x + rc*rv[i].x)*rinv, (ra*v[i].y + rc*rv[i].y)*rinv,
                       (ra*v[i].z + rc*rv[i].z)*rinv, (ra*v[i].w + rc*rv[i].w)*rinv);
            s3 += sq4(v[i]);
        }
        float zn = sqrtf(warpSumF(s3) + 1e-30f);
        if (zn > MAXN) { float ps = MAXN / zn;
            #pragma unroll
            for (int i = 0; i < 4; i++) v[i] = scl4(v[i], ps); }
    }
    #pragma unroll
    for (int i = 0; i < 4; i++) ((float4*)(h1out + row*ED))[lane + i*32] = v[i];
    float s0 = 0.0f;
    #pragma unroll
    for (int i = 0; i < 4; i++) s0 += sq4(v[i]);
    float n0 = sqrtf(warpSumF(s0) + 1e-30f);
    float lf = atanhf(fminf(n0, MAXN)) / n0;
    float sm = 0.0f;
    #pragma unroll
    for (int i = 0; i < 4; i++) { v[i] = scl4(v[i], lf); sm += v[i].x + v[i].y + v[i].z + v[i].w; }
    float mu = warpSumF(sm) * (1.0f / ED);
    float vv = 0.0f;
    #pragma unroll
    for (int i = 0; i < 4; i++) {
        float4 d; VOP4(d, v[i].x-mu, v[i].y-mu, v[i].z-mu, v[i].w-mu);
        vv += sq4(d);
    }
    float var = warpSumF(vv) * (1.0f / ED);
    float inv = rsqrtf(var + 1e-5f);
    float s2 = 0.0f;
    #pragma unroll
    for (int i = 0; i < 4; i++) {
        float4 gg = ((const float4*)g)[lane + i*32], bb = ((const float4*)bln)[lane + i*32];
        VOP4(v[i], (v[i].x-mu)*inv*gg.x + bb.x, (v[i].y-mu)*inv*gg.y + bb.y,
                   (v[i].z-mu)*inv*gg.z + bb.z, (v[i].w-mu)*inv*gg.w + bb.w);
        s2 += sq4(v[i]);
    }
    float ny = sqrtf(warpSumF(s2) + 1e-30f);
    float ef = tanhf(ny) / ny;
    #pragma unroll
    for (int i = 0; i < 4; i++) v[i] = scl4(v[i], ef);
    {
        float s3 = 0.0f;
        #pragma unroll
        for (int i = 0; i < 4; i++) s3 += sq4(v[i]);
        float n = sqrtf(warpSumF(s3) + 1e-30f);
        if (n > MAXN) { float ps = MAXN / n;
            #pragma unroll
            for (int i = 0; i < 4; i++) v[i] = scl4(v[i], ps); }
    }
    float s4 = 0.0f;
    #pragma unroll
    for (int i = 0; i < 4; i++) {
        write_split4(v[i], oh + row*ED, ol + row*ED, (lane + i*32)*2);
        s4 += sq4(v[i]);
    }
    float nf = sqrtf(warpSumF(s4) + 1e-30f);
    if (lane == 0) out_norm[row] = nf;
}

// ---------------- fc1 epilogue: warp-per-row over FD=2048 ----------------
__global__ void __launch_bounds__(128) manlin_fc1_w(
    const float* __restrict__ mx, const float* __restrict__ xnb,
    const float* __restrict__ bias,
    __nv_bfloat16* __restrict__ oh, __nv_bfloat16* __restrict__ ol,
    float* __restrict__ out_norm)
{
    const int lane = threadIdx.x & 31;
    const size_t row = blockIdx.x * 4 + (threadIdx.x >> 5);
    const float MAXN = maxnorm();
    const float4* mp = (const float4*)(mx + row * (size_t)FD);
    const float4* bp = (const float4*)bias;
    float4 v[16];
    float ss = 0.0f;
    #pragma unroll
    for (int i = 0; i < 16; i++) { v[i] = mp[lane + i*32]; ss += sq4(v[i]); }
    float mxn = sqrtf(warpSumF(ss) + 1e-30f);
    float xn = xnb[row];
    float s = tanhf(mxn / xn * atanhf(fminf(xn, MAXN))) / mxn;
    float dxy = 0.0f, dx2 = 0.0f;
    #pragma unroll
    for (int i = 0; i < 16; i++) {
        v[i] = scl4(v[i], s);
        dxy += dot4(v[i], bp[lane + i*32]);
        dx2 += sq4(v[i]);
    }
    float xy = warpSumF(dxy);
    float x2 = warpSumF(dx2);
    float y2 = g_b2[4];
    float a = 1.0f + 2.0f*xy + y2;
    float c = 1.0f - x2;
    float invd = 1.0f / fmaxf(1.0f + 2.0f*xy + x2*y2, 1e-15f);
    float zz = 0.0f;
    #pragma unroll
    for (int i = 0; i < 16; i++) {
        float4 bv = bp[lane + i*32];
        VOP4(v[i], (a*v[i].x + c*bv.x)*invd, (a*v[i].y + c*bv.y)*invd,
                   (a*v[i].z + c*bv.z)*invd, (a*v[i].w + c*bv.w)*invd);
        zz += sq4(v[i]);
    }
    {
        float zn = sqrtf(warpSumF(zz) + 1e-30f);
        if (zn > MAXN) { float ps = MAXN / zn;
            #pragma unroll
            for (int i = 0; i < 16; i++) v[i] = scl4(v[i], ps); }
    }
    float s0 = 0.0f;
    #pragma unroll
    for (int i = 0; i < 16; i++) s0 += sq4(v[i]);
    float n = sqrtf(warpSumF(s0) + 1e-30f);
    float lf = atanhf(fminf(n, MAXN)) / n;
    float s1 = 0.0f;
    #pragma unroll
    for (int i = 0; i < 16; i++) {
        VOP4(v[i], fmaxf(lf*v[i].x, 0.0f), fmaxf(lf*v[i].y, 0.0f),
                   fmaxf(lf*v[i].z, 0.0f), fmaxf(lf*v[i].w, 0.0f));
        s1 += sq4(v[i]);
    }
    float nr = sqrtf(warpSumF(s1) + 1e-30f);
    float ef = tanhf(nr) / nr;
    float s2 = 0.0f;
    #pragma unroll
    for (int i = 0; i < 16; i++) { v[i] = scl4(v[i], ef); s2 += sq4(v[i]); }
    {
        float n2 = sqrtf(warpSumF(s2) + 1e-30f);
        if (n2 > MAXN) { float ps = MAXN / n2;
            #pragma unroll
            for (int i = 0; i < 16; i++) v[i] = scl4(v[i], ps); }
    }
    float s5 = 0.0f;
    #pragma unroll
    for (int i = 0; i < 16; i++) {
        write_split4(v[i], oh + row*(size_t)FD, ol + row*(size_t)FD, (lane + i*32)*2);
        s5 += sq4(v[i]);
    }
    float nf = sqrtf(warpSumF(s5) + 1e-30f);
    if (lane == 0) out_norm[row] = nf;
}

// ---------------- final: manlin(W2) + mob_relu + residual -> fp32 out ----------------
__global__ void __launch_bounds__(256) manlin_final_w(
    const float* __restrict__ mx, const float* __restrict__ xnb,
    const float* __restrict__ bias, int b2idx, const float* __restrict__ resid,
    float* __restrict__ outf)
{
    const int lane = threadIdx.x & 31;
    const size_t row = blockIdx.x * 8 + (threadIdx.x >> 5);
    const float MAXN = maxnorm();
    float4 v[4], bvv[4];
    float ss = 0.0f;
    #pragma unroll
    for (int i = 0; i < 4; i++) {
        v[i] = ((const float4*)(mx + row*ED))[lane + i*32];
        bvv[i] = ((const float4*)bias)[lane + i*32];
        ss += sq4(v[i]);
    }
    float mxn = sqrtf(warpSumF(ss) + 1e-30f);
    float xn = xnb[row];
    float s = tanhf(mxn / xn * atanhf(fminf(xn, MAXN))) / mxn;
    float dxy = 0.0f, dx2 = 0.0f;
    #pragma unroll
    for (int i = 0; i < 4; i++) {
        v[i] = scl4(v[i], s);
        dxy += dot4(v[i], bvv[i]);
        dx2 += sq4(v[i]);
    }
    float xy = warpSumF(dxy);
    float x2 = warpSumF(dx2);
    float y2 = g_b2[b2idx];
    float a = 1.0f + 2.0f*xy + y2;
    float c = 1.0f - x2;
    float invd = 1.0f / fmaxf(1.0f + 2.0f*xy + x2*y2, 1e-15f);
    float zz = 0.0f;
    #pragma unroll
    for (int i = 0; i < 4; i++) {
        VOP4(v[i], (a*v[i].x + c*bvv[i].x)*invd, (a*v[i].y + c*bvv[i].y)*invd,
                   (a*v[i].z + c*bvv[i].z)*invd, (a*v[i].w + c*bvv[i].w)*invd);
        zz += sq4(v[i]);
    }
    {
        float zn = sqrtf(warpSumF(zz) + 1e-30f);
        if (zn > MAXN) { float ps = MAXN / zn;
            #pragma unroll
            for (int i = 0; i < 4; i++) v[i] = scl4(v[i], ps); }
    }
    {
        float s0 = 0.0f;
        #pragma unroll
        for (int i = 0; i < 4; i++) s0 += sq4(v[i]);
        float n = sqrtf(warpSumF(s0) + 1e-30f);
        float lf = atanhf(fminf(n, MAXN)) / n;
        float s1 = 0.0f;
        #pragma unroll
        for (int i = 0; i < 4; i++) {
            VOP4(v[i], fmaxf(lf*v[i].x, 0.0f), fmaxf(lf*v[i].y, 0.0f),
                       fmaxf(lf*v[i].z, 0.0f), fmaxf(lf*v[i].w, 0.0f));
            s1 += sq4(v[i]);
        }
        float nr = sqrtf(warpSumF(s1) + 1e-30f);
        float ef = tanhf(nr) / nr;
        float s2 = 0.0f;
        #pragma unroll
        for (int i = 0; i < 4; i++) { v[i] = scl4(v[i], ef); s2 += sq4(v[i]); }
        float n2 = sqrtf(warpSumF(s2) + 1e-30f);
        if (n2 > MAXN) { float ps = MAXN / n2;
            #pragma unroll
            for (int i = 0; i < 4; i++) v[i] = scl4(v[i], ps); }
    }
    {
        float d1 = 0.0f, d2 = 0.0f, d3 = 0.0f;
        float4 rv[4];
        #pragma unroll
        for (int i = 0; i < 4; i++) {
            rv[i] = ((const float4*)(resid + row*ED))[lane + i*32];
            d1 += dot4(v[i], rv[i]);
            d2 += sq4(rv[i]);
            d3 += sq4(v[i]);
        }
        float rxy = warpSumF(d1);
        float ry2 = warpSumF(d2);
        float rx2 = warpSumF(d3);
        float ra = 1.0f + 2.0f*rxy + ry2;
        float rc = 1.0f - rx2;
        float rinv = 1.0f / fmaxf(1.0f + 2.0f*rxy + rx2*ry2, 1e-15f);
        float s3 = 0.0f;
        #pragma unroll
        for (int i = 0; i < 4; i++) {
            VOP4(v[i], (ra*v[i].x + rc*rv[i].x)*rinv, (ra*v[i].y + rc*rv[i].y)*rinv,
                       (ra*v[i].z + rc*rv[i].z)*rinv, (ra*v[i].w + rc*rv[i].w)*rinv);
            s3 += sq4(v[i]);
        }
        float zn = sqrtf(warpSumF(s3) + 1e-30f);
        if (zn > MAXN) { float ps = MAXN / zn;
            #pragma unroll
            for (int i = 0; i < 4; i++) v[i] = scl4(v[i], ps); }
    }
    #pragma unroll
    for (int i = 0; i < 4; i++) ((float4*)(outf + row*ED))[lane + i*32] = v[i];
}

// ---------------- MMA helpers ----------------
__device__ __forceinline__ void ldsm_x4(uint32_t &r0, uint32_t &r1, uint32_t &r2, uint32_t &r3, uint32_t addr) {
    asm volatile("ldmatrix.sync.aligned.m8n8.x4.shared.b16 {%0,%1,%2,%3}, [%4];"
                 : "=r"(r0), "=r"(r1), "=r"(r2), "=r"(r3) : "r"(addr));
}
__device__ __forceinline__ void ldsm_x4t(uint32_t &r0, uint32_t &r1, uint32_t &r2, uint32_t &r3, uint32_t addr) {
    asm volatile("ldmatrix.sync.aligned.m8n8.x4.trans.shared.b16 {%0,%1,%2,%3}, [%4];"
                 : "=r"(r0), "=r"(r1), "=r"(r2), "=r"(r3) : "r"(addr));
}
__device__ __forceinline__ void mma16816(float* c, const uint32_t* a, const uint32_t* b) {
    asm volatile("mma.sync.aligned.m16n8k16.row.col.f32.bf16.bf16.f32 "
                 "{%0,%1,%2,%3}, {%4,%5,%6,%7}, {%8,%9}, {%0,%1,%2,%3};"
                 : "+f"(c[0]), "+f"(c[1]), "+f"(c[2]), "+f"(c[3])
                 : "r"(a[0]), "r"(a[1]), "r"(a[2]), "r"(a[3]), "r"(b[0]), "r"(b[1]));
}
#define CP_ASYNC16(dst, src) asm volatile("cp.async.cg.shared.global [%0], [%1], 16;" :: "r"(dst), "l"(src))

// ---------------- tensor-core attention: Q/K/V in 96KB smem, forced 2 CTAs/SM ----------------
#define ATT_SMEM 98304
__global__ void __launch_bounds__(256, 2) attn_mma(
    const __nv_bfloat16* __restrict__ qh_g, const __nv_bfloat16* __restrict__ ql_g,
    float* __restrict__ o)
{
    extern __shared__ __nv_bfloat16 smbuf[];
    uint32_t smb = (uint32_t)__cvta_generic_to_shared(smbuf);
    const int tid = threadIdx.x;
    const int lane = tid & 31, w = tid >> 5;
    const int bh = blockIdx.x, b = bh >> 3, h = bh & 7;

    #pragma unroll
    for (int it = 0; it < 24; it++) {
        int idx = tid + (it << 8);
        int tensor = idx >> 10;
        int cid = idx & 1023;
        int r = cid >> 3, c = cid & 7;
        uint32_t dst = smb + tensor*16384 + r*128 + ((c ^ (r & 7)) << 4);
        const __nv_bfloat16* P = (tensor & 1) ? ql_g : qh_g;
        const __nv_bfloat16* src = P + ((size_t)r*BB + b)*QKVW + (size_t)(tensor>>1)*512 + h*HD + c*8;
        CP_ASYNC16(dst, src);
    }
    asm volatile("cp.async.commit_group;");
    asm volatile("cp.async.wait_group 0;");
    __syncthreads();

    const int quad = lane >> 3, r8 = lane & 7;

    float sc[16][4];
    #pragma unroll
    for (int n = 0; n < 16; n++)
        #pragma unroll
        for (int e = 0; e < 4; e++) sc[n][e] = 0.0f;

    #pragma unroll
    for (int kk = 0; kk < 4; kk++) {
        uint32_t qh_[4], ql_[4];
        int arow = w*16 + (quad & 1)*8 + r8;
        int achk = kk*2 + (quad >> 1);
        uint32_t aoff = (uint32_t)(arow*128 + ((achk ^ (arow & 7)) << 4));
        ldsm_x4(qh_[0], qh_[1], qh_[2], qh_[3], smb + aoff);
        ldsm_x4(ql_[0], ql_[1], ql_[2], ql_[3], smb + 16384 + aoff);
        #pragma unroll
        for (int nn = 0; nn < 8; nn++) {
            int krow = nn*16 + (quad >> 1)*8 + r8;
            int kchk = kk*2 + (quad & 1);
            uint32_t koff = (uint32_t)(krow*128 + ((kchk ^ (krow & 7)) << 4));
            uint32_t kh0[2], kh1[2], kl0[2], kl1[2];
            { uint32_t a0,a1,a2,a3; ldsm_x4(a0,a1,a2,a3, smb + 32768 + koff);
              kh0[0]=a0; kh0[1]=a1; kh1[0]=a2; kh1[1]=a3; }
            { uint32_t a0,a1,a2,a3; ldsm_x4(a0,a1,a2,a3, smb + 49152 + koff);
              kl0[0]=a0; kl0[1]=a1; kl1[0]=a2; kl1[1]=a3; }
            mma16816(sc[2*nn],   qh_, kh0);
            mma16816(sc[2*nn],   qh_, kl0);
            mma16816(sc[2*nn],   ql_, kh0);
            mma16816(sc[2*nn+1], qh_, kh1);
            mma16816(sc[2*nn+1], qh_, kl1);
            mma16816(sc[2*nn+1], ql_, kh1);
        }
    }

    float m0 = -1e30f, m1 = -1e30f;
    #pragma unroll
    for (int n = 0; n < 16; n++) {
        m0 = fmaxf(m0, fmaxf(sc[n][0], sc[n][1]));
        m1 = fmaxf(m1, fmaxf(sc[n][2], sc[n][3]));
    }
    m0 = fmaxf(m0, __shfl_xor_sync(0xffffffffu, m0, 1));
    m0 = fmaxf(m0, __shfl_xor_sync(0xffffffffu, m0, 2));
    m1 = fmaxf(m1, __shfl_xor_sync(0xffffffffu, m1, 1));
    m1 = fmaxf(m1, __shfl_xor_sync(0xffffffffu, m1, 2));
    float l0 = 0.0f, l1 = 0.0f;
    #pragma unroll
    for (int n = 0; n < 16; n++) {
        sc[n][0] = fexp((sc[n][0] - m0) * 0.125f); l0 += sc[n][0];
        sc[n][1] = fexp((sc[n][1] - m0) * 0.125f); l0 += sc[n][1];
        sc[n][2] = fexp((sc[n][2] - m1) * 0.125f); l1 += sc[n][2];
        sc[n][3] = fexp((sc[n][3] - m1) * 0.125f); l1 += sc[n][3];
    }
    l0 += __shfl_xor_sync(0xffffffffu, l0, 1);
    l0 += __shfl_xor_sync(0xffffffffu, l0, 2);
    l1 += __shfl_xor_sync(0xffffffffu, l1, 1);
    l1 += __shfl_xor_sync(0xffffffffu, l1, 2);
    float inv0 = 1.0f / l0, inv1 = 1.0f / l1;

    float oa[8][4];
    #pragma unroll
    for (int n = 0; n < 8; n++)
        #pragma unroll
        for (int e = 0; e < 4; e++) oa[n][e] = 0.0f;

    #pragma unroll
    for (int kt = 0; kt < 8; kt++) {
        uint32_t ph[4], pl[4];
        #pragma unroll
        for (int half = 0; half < 2; half++) {
            int n2 = 2*kt + half;
            float p0 = sc[n2][0], p1 = sc[n2][1], p2 = sc[n2][2], p3 = sc[n2][3];
            __nv_bfloat16 b0 = __float2bfloat16(p0), b1 = __float2bfloat16(p1);
            __nv_bfloat16 b2 = __float2bfloat16(p2), b3 = __float2bfloat16(p3);
            ph[half*2+0] = pack_bf2(p0, p1);
            ph[half*2+1] = pack_bf2(p2, p3);
            pl[half*2+0] = pack_bf2(p0 - __bfloat162float(b0), p1 - __bfloat162float(b1));
            pl[half*2+1] = pack_bf2(p2 - __bfloat162float(b2), p3 - __bfloat162float(b3));
        }
        #pragma unroll
        for (int nn = 0; nn < 4; nn++) {
            int vrow = kt*16 + (quad & 1)*8 + r8;
            int vchk = 2*nn + (quad >> 1);
            uint32_t voff = (uint32_t)(vrow*128 + ((vchk ^ (vrow & 7)) << 4));
            uint32_t vh0[2], vh1[2], vl0[2], vl1[2];
            { uint32_t a0,a1,a2,a3; ldsm_x4t(a0,a1,a2,a3, smb + 65536 + voff);
              vh0[0]=a0; vh0[1]=a1; vh1[0]=a2; vh1[1]=a3; }
            { uint32_t a0,a1,a2,a3; ldsm_x4t(a0,a1,a2,a3, smb + 81920 + voff);
              vl0[0]=a0; vl0[1]=a1; vl1[0]=a2; vl1[1]=a3; }
            mma16816(oa[2*nn],   ph, vh0);
            mma16816(oa[2*nn],   ph, vl0);
            mma16816(oa[2*nn],   pl, vh0);
            mma16816(oa[2*nn+1], ph, vh1);
            mma16816(oa[2*nn+1], ph, vl1);
            mma16816(oa[2*nn+1], pl, vh1);
        }
    }

    int g = lane >> 2, t2 = (lane & 3) * 2;
    int t0 = w*16 + g;
    #pragma unroll
    for (int n = 0; n < 8; n++) {
        size_t base0 = ((size_t)t0*BB + b)*ED + (size_t)h*HD + n*8 + t2;
        size_t base1 = ((size_t)(t0+8)*BB + b)*ED + (size_t)h*HD + n*8 + t2;
        *(float2*)(o + base0) = make_float2(oa[n][0]*inv0, oa[n][1]*inv0);
        *(float2*)(o + base1) = make_float2(oa[n][2]*inv1, oa[n][3]*inv1);
    }
}

// ================= bf16x3 HMMA GEMM (R13 scheduling: interleaved A/B loads) =================
#define BM 128
#define BN 128
#define BK 32
#define TEN_B   8192
#define STAGE_B (4*TEN_B)
#define GEMM_SMEM (3*STAGE_B)

__device__ __forceinline__ uint32_t saddr(int r, int colElem) {
    return (uint32_t)(r*64 + ((((colElem >> 3) ^ ((r >> 1) & 3))) << 4));
}

__global__ void __launch_bounds__(256, 2) gemm_bf16x3(
    const __nv_bfloat16* __restrict__ Ah, const __nv_bfloat16* __restrict__ Al,
    const __nv_bfloat16* __restrict__ Wh, const __nv_bfloat16* __restrict__ Wl,
    float* __restrict__ C, int M, int N, int K)
{
    extern __shared__ __nv_bfloat16 smbuf[];
    const int tid = threadIdx.x;
    const int lane = tid & 31, w = tid >> 5;
    const int wm = w & 1, wn = w >> 1;
    const int rowBase = blockIdx.y * BM;
    const int colBase = blockIdx.x * BN;
    uint32_t smbase = (uint32_t)__cvta_generic_to_shared(smbuf);

    float acc[4][4][4];
    #pragma unroll
    for (int i = 0; i < 4; i++)
        #pragma unroll
        for (int j = 0; j < 4; j++)
            #pragma unroll
            for (int e = 0; e < 4; e++) acc[i][j][e] = 0.0f;

    auto load_stage = [&](int st, int k0) {
        uint32_t base = smbase + st * STAGE_B;
        #pragma unroll
        for (int it = 0; it < 8; it++) {
            int idx = tid + (it << 8);
            int tensor = idx >> 9;
            int cid = idx & 511;
            int r = cid >> 2, c = cid & 3;
            uint32_t dst = base + tensor * TEN_B
                         + (uint32_t)(r*64 + ((c ^ ((r >> 1) & 3)) << 4));
            const __nv_bfloat16* src;
            if (tensor == 0)      src = Ah + (size_t)(rowBase + r) * K + k0 + c * 8;
            else if (tensor == 1) src = Al + (size_t)(rowBase + r) * K + k0 + c * 8;
            else if (tensor == 2) src = Wh + (size_t)(colBase + r) * K + k0 + c * 8;
            else                  src = Wl + (size_t)(colBase + r) * K + k0 + c * 8;
            CP_ASYNC16(dst, src);
        }
        asm volatile("cp.async.commit_group;");
    };

    auto compute_stage = [&](int st) {
        uint32_t base = smbase + st * STAGE_B;
        uint32_t aH = base;
        uint32_t aL = base + 1*TEN_B;
        uint32_t wH = base + 2*TEN_B;
        uint32_t wL = base + 3*TEN_B;
        const int quad = lane >> 3, r8 = lane & 7;
        #pragma unroll
        for (int kk = 0; kk < BK; kk += 16) {
            uint32_t ah[4][4], al[4][4], bh[4][2], bl[4][2];
            #pragma unroll
            for (int i = 0; i < 4; i++) {
                int row = wm*64 + i*16 + (quad & 1)*8 + r8;
                int col = kk + (quad >> 1)*8;
                uint32_t off = saddr(row, col);
                ldsm_x4(ah[i][0], ah[i][1], ah[i][2], ah[i][3], aH + off);
                ldsm_x4(al[i][0], al[i][1], al[i][2], al[i][3], aL + off);
            }
            #pragma unroll
            for (int jj = 0; jj < 2; jj++) {
                int nr = wn*32 + jj*16 + (quad >> 1)*8 + r8;
                int kc = kk + (quad & 1)*8;
                uint32_t off = saddr(nr, kc);
                uint32_t a0,a1,a2,a3;
                ldsm_x4(a0,a1,a2,a3, wH + off);
                bh[2*jj][0]=a0; bh[2*jj][1]=a1; bh[2*jj+1][0]=a2; bh[2*jj+1][1]=a3;
                ldsm_x4(a0,a1,a2,a3, wL + off);
                bl[2*jj][0]=a0; bl[2*jj][1]=a1; bl[2*jj+1][0]=a2; bl[2*jj+1][1]=a3;
            }
            #pragma unroll
            for (int i = 0; i < 4; i++)
                #pragma unroll
                for (int j = 0; j < 4; j++) mma16816(acc[i][j], ah[i], bh[j]);
            #pragma unroll
            for (int i = 0; i < 4; i++)
                #pragma unroll
                for (int j = 0; j < 4; j++) mma16816(acc[i][j], ah[i], bl[j]);
            #pragma unroll
            for (int i = 0; i < 4; i++)
                #pragma unroll
                for (int j = 0; j < 4; j++) mma16816(acc[i][j], al[i], bh[j]);
        }
    };

    const int nkb = K / BK;
    load_stage(0, 0);
    load_stage(1, BK);
    for (int kb = 0; kb < nkb; kb++) {
        if (kb == nkb - 1) { asm volatile("cp.async.wait_group 0;"); }
        else               { asm volatile("cp.async.wait_group 1;"); }
        __syncthreads();
        if (kb + 2 < nkb) load_stage((kb + 2) % 3, (kb + 2) * BK);
        compute_stage(kb % 3);
    }

    const int g = lane >> 2, tg = lane & 3;
    #pragma unroll
    for (int i = 0; i < 4; i++) {
        int row = rowBase + wm*64 + i*16 + g;
        #pragma unroll
        for (int j = 0; j < 4; j++) {
            int col = colBase + wn*32 + j*8 + tg*2;
            *(float2*)(C + (size_t)row * N + col)       = make_float2(acc[i][j][0], acc[i][j][1]);
            *(float2*)(C + (size_t)(row + 8) * N + col) = make_float2(acc[i][j][2], acc[i][j][3]);
        }
    }
}

// ---------------- launch ----------------
extern "C" void kernel_launch(void* const* d_in, const int* in_sizes, int n_in,
                              void* d_out, int out_size)
{
    const float* x    = (const float*)d_in[0];
    const float* l1g  = (const float*)d_in[1];
    const float* l1b  = (const float*)d_in[2];
    const float* l2g  = (const float*)d_in[3];
    const float* l2b  = (const float*)d_in[4];
    const float* Wq   = (const float*)d_in[5];
    const float* bq   = (const float*)d_in[6];
    const float* Wk   = (const float*)d_in[7];
    const float* bk   = (const float*)d_in[8];
    const float* Wv   = (const float*)d_in[9];
    const float* bv   = (const float*)d_in[10];
    const float* Wo   = (const float*)d_in[11];
    const float* bo   = (const float*)d_in[12];
    const float* W1   = (const float*)d_in[13];
    const float* b1   = (const float*)d_in[14];
    const float* W2   = (const float*)d_in[15];
    const float* b2   = (const float*)d_in[16];
    float* out = (float*)d_out;

    float *qkv, *ob, *h1, *big, *n0, *no, *nh2, *nh3, *bsq;
    __nv_bfloat16 *xh, *xl, *wh, *wl;
    cudaGetSymbolAddress((void**)&qkv, g_qkv);
    cudaGetSymbolAddress((void**)&ob,  g_o);
    cudaGetSymbolAddress((void**)&h1,  g_h1);
    cudaGetSymbolAddress((void**)&big, g_big);
    cudaGetSymbolAddress((void**)&xh,  g_xh);
    cudaGetSymbolAddress((void**)&xl,  g_xl);
    cudaGetSymbolAddress((void**)&wh,  g_wh);
    cudaGetSymbolAddress((void**)&wl,  g_wl);
    cudaGetSymbolAddress((void**)&n0,  g_n0);
    cudaGetSymbolAddress((void**)&no,  g_no);
    cudaGetSymbolAddress((void**)&nh2, g_nh2);
    cudaGetSymbolAddress((void**)&nh3, g_nh3);
    cudaGetSymbolAddress((void**)&bsq, g_b2);

    cudaFuncSetAttribute(gemm_bf16x3, cudaFuncAttributeMaxDynamicSharedMemorySize, GEMM_SMEM);
    cudaFuncSetAttribute(attn_mma, cudaFuncAttributeMaxDynamicSharedMemorySize, ATT_SMEM);

    prep_kernel<<<PREP_BLOCKS, 256>>>(Wq, Wk, Wv, Wo, W1, W2,
                                      bq, bk, bv, bo, b1, b2,
                                      x, l1g, l1b, wh, wl, xh, xl, n0, bsq);

    gemm_bf16x3<<<dim3(QKVW/BN, NR/BM), 256, GEMM_SMEM>>>(xh, xl, wh + WQ0, wl + WQ0, qkv, NR, QKVW, ED);
    manlin_qkv_w<<<dim3(NR/8, 3), 256>>>(qkv, n0, bq, bk, bv, xh, xl);

    attn_mma<<<BB * NH, 256, ATT_SMEM>>>(xh, xl, ob);
    expmap_w<<<NR/8, 256>>>(ob, xh, xl, no);

    gemm_bf16x3<<<dim3(ED/BN, NR/BM), 256, GEMM_SMEM>>>(xh, xl, wh + WO0, wl + WO0, big, NR, ED, ED);
    manlin_ln_w<<<NR/8, 256>>>(big, no, bo, 3, x, h1, l2g, l2b, xh, xl, nh2);

    gemm_bf16x3<<<dim3(FD/BN, NR/BM), 256, GEMM_SMEM>>>(xh, xl, wh + W10, wl + W10, big, NR, FD, ED);
    manlin_fc1_w<<<NR/4, 128>>>(big, nh2, b1, xh, xl, nh3);

    gemm_bf16x3<<<dim3(ED/BN, NR/BM), 256, GEMM_SMEM>>>(xh, xl, wh + W20, wl + W20, qkv, NR, ED, FD);
    manlin_final_w<<<NR/8, 256>>>(qkv, nh3, b2, 5, h1, out);
}

// round 16
// speedup vs baseline: 1.0295x; 1.0072x over previous
#include <cuda_runtime.h>
#include <cuda_bf16.h>
#include <math.h>
#include <stdint.h>

// ---------------- problem constants ----------------
#define SEQ 128
#define BB  256
#define ED  512
#define FD  2048
#define NH  8
#define HD  64
#define NR  (SEQ*BB)   // 32768 rows
#define QKVW 1536      // fused qkv row width

static __device__ __forceinline__ float maxnorm() { return (float)(1.0 - 1e-5); }

// ---------------- scratch ----------------
__device__ float g_qkv[(size_t)NR*QKVW];
__device__ float g_o  [(size_t)NR*ED];
__device__ float g_h1 [(size_t)NR*ED];
__device__ float g_big[(size_t)NR*FD];
__device__ __nv_bfloat16 g_xh[(size_t)NR*FD];
__device__ __nv_bfloat16 g_xl[(size_t)NR*FD];
__device__ __nv_bfloat16 g_wh[(size_t)3*1024*1024];
__device__ __nv_bfloat16 g_wl[(size_t)3*1024*1024];
__device__ float g_n0 [NR];
__device__ float g_no [NR];
__device__ float g_nh2[NR];
__device__ float g_nh3[NR];
__device__ float g_b2 [8];

#define WQ0 0
#define WK0 262144
#define WV0 524288
#define WO0 786432
#define W10 1048576
#define W20 2097152

// ---------------- reductions ----------------
template <int T>
__device__ __forceinline__ float blockSumF(float v) {
    __shared__ float sh[T / 32];
    #pragma unroll
    for (int o = 16; o > 0; o >>= 1) v += __shfl_xor_sync(0xffffffffu, v, o);
    int lane = threadIdx.x & 31, w = threadIdx.x >> 5;
    if (lane == 0) sh[w] = v;
    __syncthreads();
    if (threadIdx.x < 32) {
        float t = (threadIdx.x < T / 32) ? sh[threadIdx.x] : 0.0f;
        #pragma unroll
        for (int o = 16; o > 0; o >>= 1) t += __shfl_xor_sync(0xffffffffu, t, o);
        if (threadIdx.x == 0) sh[0] = t;
    }
    __syncthreads();
    float r = sh[0];
    __syncthreads();
    return r;
}
__device__ __forceinline__ float warpSumF(float v) {
    #pragma unroll
    for (int o = 16; o > 0; o >>= 1) v += __shfl_xor_sync(0xffffffffu, v, o);
    return v;
}

__device__ __forceinline__ void split1(float x, __nv_bfloat16 &h, __nv_bfloat16 &l) {
    h = __float2bfloat16(x);
    l = __float2bfloat16(x - __bfloat162float(h));
}
__device__ __forceinline__ uint32_t pack_bf2(float a, float b) {
    __nv_bfloat162 t(__float2bfloat16(a), __float2bfloat16(b));
    return *(uint32_t*)&t;
}

// FMA-pipe exp of (s * 0.125): scale folded into log2e constant.
// Valid for |s| <= ~38 (scores are bounded by atanh(1-1e-5)^2 ≈ 37.5).
__device__ __forceinline__ float fexp8(float s) {
    float y = s * 0.18033688011112042f;   // 0.125 * log2(e)
    y = fmaxf(y, -126.0f);
    float fl = floorf(y);
    float f = y - fl;
    float p = 1.5252734e-5f;
    p = fmaf(p, f, 1.5403530e-4f);
    p = fmaf(p, f, 1.3333558e-3f);
    p = fmaf(p, f, 9.6181291e-3f);
    p = fmaf(p, f, 5.5504109e-2f);
    p = fmaf(p, f, 2.4022651e-1f);
    p = fmaf(p, f, 6.9314718e-1f);
    p = fmaf(p, f, 1.0f);
    return __int_as_float(__float_as_int(p) + (((int)fl) << 23));
}

// vector helpers
#define VOP4(dst, ex, ey, ez, ew) do { dst.x=(ex); dst.y=(ey); dst.z=(ez); dst.w=(ew); } while(0)
__device__ __forceinline__ float dot4(float4 a, float4 b) { return a.x*b.x + a.y*b.y + a.z*b.z + a.w*b.w; }
__device__ __forceinline__ float sq4(float4 a) { return dot4(a, a); }
__device__ __forceinline__ float4 scl4(float4 a, float s) { float4 r; VOP4(r, a.x*s, a.y*s, a.z*s, a.w*s); return r; }

__device__ __forceinline__ void write_split4(float4 v, __nv_bfloat16* oh, __nv_bfloat16* ol, int idx2) {
    __nv_bfloat16 h0,l0,h1,l1,h2,l2,h3,l3;
    split1(v.x,h0,l0); split1(v.y,h1,l1); split1(v.z,h2,l2); split1(v.w,h3,l3);
    __nv_bfloat162 ph0(h0,h1), ph1(h2,h3), pl0(l0,l1), pl1(l2,l3);
    uint2 hh = make_uint2(*(uint32_t*)&ph0, *(uint32_t*)&ph1);
    uint2 ll = make_uint2(*(uint32_t*)&pl0, *(uint32_t*)&pl1);
    *(uint2*)((__nv_bfloat162*)oh + idx2) = hh;   // idx2 even -> 8B aligned
    *(uint2*)((__nv_bfloat162*)ol + idx2) = ll;
}

// ================= fused prep: weight splits + bias norms + ln1 (one launch) =================
#define PREP_BLOCKS (3072 + 6 + NR/8)
__global__ void __launch_bounds__(256) prep_kernel(
    const float* Wq, const float* Wk, const float* Wv,
    const float* Wo, const float* W1, const float* W2,
    const float* bq, const float* bk, const float* bv,
    const float* bo, const float* b1, const float* b2,
    const float* __restrict__ x, const float* __restrict__ l1g, const float* __restrict__ l1b,
    __nv_bfloat16* __restrict__ wh, __nv_bfloat16* __restrict__ wl,
    __nv_bfloat16* __restrict__ xh, __nv_bfloat16* __restrict__ xl,
    float* __restrict__ n0out, float* __restrict__ bsq)
{
    const int bid = blockIdx.x;
    if (bid < 3072) {
        const float* src; size_t off; int sub;
        if (bid < 1024) {
            sub = bid & 255;
            switch (bid >> 8) {
                case 0: src = Wq; off = WQ0; break;
                case 1: src = Wk; off = WK0; break;
                case 2: src = Wv; off = WV0; break;
                default: src = Wo; off = WO0; break;
            }
        } else if (bid < 2048) { src = W1; off = W10; sub = bid - 1024; }
        else                   { src = W2; off = W20; sub = bid - 2048; }
        int i = sub * 256 + threadIdx.x;
        float4 v = ((const float4*)src)[i];
        __nv_bfloat16 h0,l0,h1,l1,h2,l2,h3,l3;
        split1(v.x, h0, l0); split1(v.y, h1, l1);
        split1(v.z, h2, l2); split1(v.w, h3, l3);
        __nv_bfloat162 ph0(h0,h1), ph1(h2,h3), pl0(l0,l1), pl1(l2,l3);
        uint2 hh = make_uint2(*(uint32_t*)&ph0, *(uint32_t*)&ph1);
        uint2 ll = make_uint2(*(uint32_t*)&pl0, *(uint32_t*)&pl1);
        *(uint2*)((__nv_bfloat162*)(wh + off) + i*2) = hh;
        *(uint2*)((__nv_bfloat162*)(wl + off) + i*2) = ll;
        return;
    }
    if (bid < 3078) {
        int task = bid - 3072;
        const float* p; int n;
        switch (task) {
            case 0: p = bq; n = ED; break;
            case 1: p = bk; n = ED; break;
            case 2: p = bv; n = ED; break;
            case 3: p = bo; n = ED; break;
            case 4: p = b1; n = FD; break;
            default: p = b2; n = ED; break;
        }
        float s = 0.0f;
        for (int i = threadIdx.x; i < n; i += 256) { float xx = p[i]; s += xx * xx; }
        s = blockSumF<256>(s);
        if (threadIdx.x == 0) bsq[task] = s;
        return;
    }
    // ln1 warp-per-row
    const int lane = threadIdx.x & 31;
    const size_t row = (size_t)(bid - 3078) * 8 + (threadIdx.x >> 5);
    const float MAXN = maxnorm();
    const float4* xp = (const float4*)(x + row * ED);
    float4 v[4];
    float ss = 0.0f;
    #pragma unroll
    for (int i = 0; i < 4; i++) { v[i] = xp[lane + i*32]; ss += sq4(v[i]); }
    float nn0 = sqrtf(warpSumF(ss) + 1e-30f);
    float lf = atanhf(fminf(nn0, MAXN)) / nn0;
    float sm = 0.0f;
    #pragma unroll
    for (int i = 0; i < 4; i++) { v[i] = scl4(v[i], lf); sm += v[i].x + v[i].y + v[i].z + v[i].w; }
    float mu = warpSumF(sm) * (1.0f / ED);
    float vv = 0.0f;
    #pragma unroll
    for (int i = 0; i < 4; i++) {
        float4 d; VOP4(d, v[i].x-mu, v[i].y-mu, v[i].z-mu, v[i].w-mu);
        vv += sq4(d);
    }
    float var = warpSumF(vv) * (1.0f / ED);
    float inv = rsqrtf(var + 1e-5f);
    float s2 = 0.0f;
    #pragma unroll
    for (int i = 0; i < 4; i++) {
        float4 gg = ((const float4*)l1g)[lane + i*32], bb = ((const float4*)l1b)[lane + i*32];
        VOP4(v[i], (v[i].x-mu)*inv*gg.x + bb.x, (v[i].y-mu)*inv*gg.y + bb.y,
                   (v[i].z-mu)*inv*gg.z + bb.z, (v[i].w-mu)*inv*gg.w + bb.w);
        s2 += sq4(v[i]);
    }
    float ny = sqrtf(warpSumF(s2) + 1e-30f);
    float ef = tanhf(ny) / ny;
    float s4 = 0.0f;
    #pragma unroll
    for (int i = 0; i < 4; i++) {
        v[i] = scl4(v[i], ef);
        write_split4(v[i], xh + row*ED, xl + row*ED, (lane + i*32)*2);
        s4 += sq4(v[i]);
    }
    float nf = sqrtf(warpSumF(s4) + 1e-30f);
    if (lane == 0) n0out[row] = nf;
}

// ================= warp-per-row kernels =================

// ---------------- expmap0 ----------------
__global__ void __launch_bounds__(256) expmap_w(
    const float* __restrict__ x, __nv_bfloat16* __restrict__ oh, __nv_bfloat16* __restrict__ ol,
    float* __restrict__ out_norm)
{
    const int lane = threadIdx.x & 31;
    const size_t row = blockIdx.x * 8 + (threadIdx.x >> 5);
    const float4* xp = (const float4*)(x + row * ED);
    float4 v[4];
    float ss = 0.0f;
    #pragma unroll
    for (int i = 0; i < 4; i++) { v[i] = xp[lane + i*32]; ss += sq4(v[i]); }
    float n = sqrtf(warpSumF(ss) + 1e-30f);
    float ef = tanhf(n) / n;
    float s2 = 0.0f;
    #pragma unroll
    for (int i = 0; i < 4; i++) {
        v[i] = scl4(v[i], ef);
        write_split4(v[i], oh + row*ED, ol + row*ED, (lane + i*32)*2);
        s2 += sq4(v[i]);
    }
    float nf = sqrtf(warpSumF(s2) + 1e-30f);
    if (lane == 0) out_norm[row] = nf;
}

// ---------------- q/k/v manifold epilogue ----------------
__global__ void __launch_bounds__(256) manlin_qkv_w(
    const float* __restrict__ qkvf, const float* __restrict__ xnb,
    const float* __restrict__ bq, const float* __restrict__ bk, const float* __restrict__ bv,
    __nv_bfloat16* __restrict__ oh, __nv_bfloat16* __restrict__ ol)
{
    const int lane = threadIdx.x & 31;
    const size_t row = blockIdx.x * 8 + (threadIdx.x >> 5);
    const int seg = blockIdx.y;
    const float MAXN = maxnorm();
    const float* bias = (seg == 0) ? bq : (seg == 1) ? bk : bv;
    const float4* base = (const float4*)(qkvf + row * (size_t)QKVW + seg * 512);
    float4 v[4], bvv[4];
    float ss = 0.0f;
    #pragma unroll
    for (int i = 0; i < 4; i++) {
        v[i] = base[lane + i*32];
        bvv[i] = ((const float4*)bias)[lane + i*32];
        ss += sq4(v[i]);
    }
    float mxn = sqrtf(warpSumF(ss) + 1e-30f);
    float xn = xnb[row];
    float s = tanhf(mxn / xn * atanhf(fminf(xn, MAXN))) / mxn;
    float dxy = 0.0f, dx2 = 0.0f;
    #pragma unroll
    for (int i = 0; i < 4; i++) {
        v[i] = scl4(v[i], s);
        dxy += dot4(v[i], bvv[i]);
        dx2 += sq4(v[i]);
    }
    float xy = warpSumF(dxy);
    float x2 = warpSumF(dx2);
    float y2 = g_b2[seg];
    float a = 1.0f + 2.0f*xy + y2;
    float c = 1.0f - x2;
    float invd = 1.0f / fmaxf(1.0f + 2.0f*xy + x2*y2, 1e-15f);
    float zz = 0.0f;
    #pragma unroll
    for (int i = 0; i < 4; i++) {
        VOP4(v[i], (a*v[i].x + c*bvv[i].x)*invd, (a*v[i].y + c*bvv[i].y)*invd,
                   (a*v[i].z + c*bvv[i].z)*invd, (a*v[i].w + c*bvv[i].w)*invd);
        zz += sq4(v[i]);
    }
    float zn = sqrtf(warpSumF(zz) + 1e-30f);
    if (zn > MAXN) {
        float ps = MAXN / zn;
        #pragma unroll
        for (int i = 0; i < 4; i++) v[i] = scl4(v[i], ps);
    }
    float s0 = 0.0f;
    #pragma unroll
    for (int i = 0; i < 4; i++) s0 += sq4(v[i]);
    float n = sqrtf(warpSumF(s0) + 1e-30f);
    float lf = atanhf(fminf(n, MAXN)) / n;
    size_t ob = row * (size_t)QKVW + seg * 512;
    #pragma unroll
    for (int i = 0; i < 4; i++) {
        v[i] = scl4(v[i], lf);
        write_split4(v[i], oh + ob, ol + ob, (lane + i*32)*2);
    }
}

// ---------------- fused: manlin(Wo)+residual -> ln2 -> splits ----------------
__global__ void __launch_bounds__(256) manlin_ln_w(
    const float* __restrict__ mx, const float* __restrict__ xnb,
    const float* __restrict__ bias, int b2idx, const float* __restrict__ resid,
    float* __restrict__ h1out,
    const float* __restrict__ g, const float* __restrict__ bln,
    __nv_bfloat16* __restrict__ oh, __nv_bfloat16* __restrict__ ol,
    float* __restrict__ out_norm)
{
    const int lane = threadIdx.x & 31;
    const size_t row = blockIdx.x * 8 + (threadIdx.x >> 5);
    const float MAXN = maxnorm();
    float4 v[4], bvv[4];
    float ss = 0.0f;
    #pragma unroll
    for (int i = 0; i < 4; i++) {
        v[i] = ((const float4*)(mx + row*ED))[lane + i*32];
        bvv[i] = ((const float4*)bias)[lane + i*32];
        ss += sq4(v[i]);
    }
    float mxn = sqrtf(warpSumF(ss) + 1e-30f);
    float xn = xnb[row];
    float s = tanhf(mxn / xn * atanhf(fminf(xn, MAXN))) / mxn;
    float dxy = 0.0f, dx2 = 0.0f;
    #pragma unroll
    for (int i = 0; i < 4; i++) {
        v[i] = scl4(v[i], s);
        dxy += dot4(v[i], bvv[i]);
        dx2 += sq4(v[i]);
    }
    float xy = warpSumF(dxy);
    float x2 = warpSumF(dx2);
    float y2 = g_b2[b2idx];
    float a = 1.0f + 2.0f*xy + y2;
    float c = 1.0f - x2;
    float invd = 1.0f / fmaxf(1.0f + 2.0f*xy + x2*y2, 1e-15f);
    float zz = 0.0f;
    #pragma unroll
    for (int i = 0; i < 4; i++) {
        VOP4(v[i], (a*v[i].x + c*bvv[i].x)*invd, (a*v[i].y + c*bvv[i].y)*invd,
                   (a*v[i].z + c*bvv[i].z)*invd, (a*v[i].w + c*bvv[i].w)*invd);
        zz += sq4(v[i]);
    }
    {
        float zn = sqrtf(warpSumF(zz) + 1e-30f);
        if (zn > MAXN) { float ps = MAXN / zn;
            #pragma unroll
            for (int i = 0; i < 4; i++) v[i] = scl4(v[i], ps); }
    }
    {
        float d1 = 0.0f, d2 = 0.0f, d3 = 0.0f;
        float4 rv[4];
        #pragma unroll
        for (int i = 0; i < 4; i++) {
            rv[i] = ((const float4*)(resid + row*ED))[lane + i*32];
            d1 += dot4(v[i], rv[i]);
            d2 += sq4(rv[i]);
            d3 += sq4(v[i]);
        }
        float rxy = warpSumF(d1);
        float ry2 = warpSumF(d2);
        float rx2 = warpSumF(d3);
        float ra = 1.0f + 2.0f*rxy + ry2;
        float rc = 1.0f - rx2;
        float rinv = 1.0f / fmaxf(1.0f + 2.0f*rxy + rx2*ry2, 1e-15f);
        float s3 = 0.0f;
        #pragma unroll
        for (int i = 0; i < 4; i++) {
            VOP4(v[i], (ra*v[i].x + rc*rv[i].x)*rinv, (ra*v[i].y + rc*rv[i].y)*rinv,
                       (ra*v[i].z + rc*rv[i].z)*rinv, (ra*v[i].w + rc*rv[i].w)*rinv);
            s3 += sq4(v[i]);
        }
        float zn = sqrtf(warpSumF(s3) + 1e-30f);
        if (zn > MAXN) { float ps = MAXN / zn;
            #pragma unroll
            for (int i = 0; i < 4; i++) v[i] = scl4(v[i], ps); }
    }
    #pragma unroll
    for (int i = 0; i < 4; i++) ((float4*)(h1out + row*ED))[lane + i*32] = v[i];
    float s0 = 0.0f;
    #pragma unroll
    for (int i = 0; i < 4; i++) s0 += sq4(v[i]);
    float n0 = sqrtf(warpSumF(s0) + 1e-30f);
    float lf = atanhf(fminf(n0, MAXN)) / n0;
    float sm = 0.0f;
    #pragma unroll
    for (int i = 0; i < 4; i++) { v[i] = scl4(v[i], lf); sm += v[i].x + v[i].y + v[i].z + v[i].w; }
    float mu = warpSumF(sm) * (1.0f / ED);
    float vv = 0.0f;
    #pragma unroll
    for (int i = 0; i < 4; i++) {
        float4 d; VOP4(d, v[i].x-mu, v[i].y-mu, v[i].z-mu, v[i].w-mu);
        vv += sq4(d);
    }
    float var = warpSumF(vv) * (1.0f / ED);
    float inv = rsqrtf(var + 1e-5f);
    float s2 = 0.0f;
    #pragma unroll
    for (int i = 0; i < 4; i++) {
        float4 gg = ((const float4*)g)[lane + i*32], bb = ((const float4*)bln)[lane + i*32];
        VOP4(v[i], (v[i].x-mu)*inv*gg.x + bb.x, (v[i].y-mu)*inv*gg.y + bb.y,
                   (v[i].z-mu)*inv*gg.z + bb.z, (v[i].w-mu)*inv*gg.w + bb.w);
        s2 += sq4(v[i]);
    }
    float ny = sqrtf(warpSumF(s2) + 1e-30f);
    float ef = tanhf(ny) / ny;
    #pragma unroll
    for (int i = 0; i < 4; i++) v[i] = scl4(v[i], ef);
    {
        float s3 = 0.0f;
        #pragma unroll
        for (int i = 0; i < 4; i++) s3 += sq4(v[i]);
        float n = sqrtf(warpSumF(s3) + 1e-30f);
        if (n > MAXN) { float ps = MAXN / n;
            #pragma unroll
            for (int i = 0; i < 4; i++) v[i] = scl4(v[i], ps); }
    }
    float s4 = 0.0f;
    #pragma unroll
    for (int i = 0; i < 4; i++) {
        write_split4(v[i], oh + row*ED, ol + row*ED, (lane + i*32)*2);
        s4 += sq4(v[i]);
    }
    float nf = sqrtf(warpSumF(s4) + 1e-30f);
    if (lane == 0) out_norm[row] = nf;
}

// ---------------- fc1 epilogue: warp-per-row over FD=2048 ----------------
__global__ void __launch_bounds__(128) manlin_fc1_w(
    const float* __restrict__ mx, const float* __restrict__ xnb,
    const float* __restrict__ bias,
    __nv_bfloat16* __restrict__ oh, __nv_bfloat16* __restrict__ ol,
    float* __restrict__ out_norm)
{
    const int lane = threadIdx.x & 31;
    const size_t row = blockIdx.x * 4 + (threadIdx.x >> 5);
    const float MAXN = maxnorm();
    const float4* mp = (const float4*)(mx + row * (size_t)FD);
    const float4* bp = (const float4*)bias;
    float4 v[16];
    float ss = 0.0f;
    #pragma unroll
    for (int i = 0; i < 16; i++) { v[i] = mp[lane + i*32]; ss += sq4(v[i]); }
    float mxn = sqrtf(warpSumF(ss) + 1e-30f);
    float xn = xnb[row];
    float s = tanhf(mxn / xn * atanhf(fminf(xn, MAXN))) / mxn;
    float dxy = 0.0f, dx2 = 0.0f;
    #pragma unroll
    for (int i = 0; i < 16; i++) {
        v[i] = scl4(v[i], s);
        dxy += dot4(v[i], bp[lane + i*32]);
        dx2 += sq4(v[i]);
    }
    float xy = warpSumF(dxy);
    float x2 = warpSumF(dx2);
    float y2 = g_b2[4];
    float a = 1.0f + 2.0f*xy + y2;
    float c = 1.0f - x2;
    float invd = 1.0f / fmaxf(1.0f + 2.0f*xy + x2*y2, 1e-15f);
    float zz = 0.0f;
    #pragma unroll
    for (int i = 0; i < 16; i++) {
        float4 bv = bp[lane + i*32];
        VOP4(v[i], (a*v[i].x + c*bv.x)*invd, (a*v[i].y + c*bv.y)*invd,
                   (a*v[i].z + c*bv.z)*invd, (a*v[i].w + c*bv.w)*invd);
        zz += sq4(v[i]);
    }
    {
        float zn = sqrtf(warpSumF(zz) + 1e-30f);
        if (zn > MAXN) { float ps = MAXN / zn;
            #pragma unroll
            for (int i = 0; i < 16; i++) v[i] = scl4(v[i], ps); }
    }
    float s0 = 0.0f;
    #pragma unroll
    for (int i = 0; i < 16; i++) s0 += sq4(v[i]);
    float n = sqrtf(warpSumF(s0) + 1e-30f);
    float lf = atanhf(fminf(n, MAXN)) / n;
    float s1 = 0.0f;
    #pragma unroll
    for (int i = 0; i < 16; i++) {
        VOP4(v[i], fmaxf(lf*v[i].x, 0.0f), fmaxf(lf*v[i].y, 0.0f),
                   fmaxf(lf*v[i].z, 0.0f), fmaxf(lf*v[i].w, 0.0f));
        s1 += sq4(v[i]);
    }
    float nr = sqrtf(warpSumF(s1) + 1e-30f);
    float ef = tanhf(nr) / nr;
    float s2 = 0.0f;
    #pragma unroll
    for (int i = 0; i < 16; i++) { v[i] = scl4(v[i], ef); s2 += sq4(v[i]); }
    {
        float n2 = sqrtf(warpSumF(s2) + 1e-30f);
        if (n2 > MAXN) { float ps = MAXN / n2;
            #pragma unroll
            for (int i = 0; i < 16; i++) v[i] = scl4(v[i], ps); }
    }
    float s5 = 0.0f;
    #pragma unroll
    for (int i = 0; i < 16; i++) {
        write_split4(v[i], oh + row*(size_t)FD, ol + row*(size_t)FD, (lane + i*32)*2);
        s5 += sq4(v[i]);
    }
    float nf = sqrtf(warpSumF(s5) + 1e-30f);
    if (lane == 0) out_norm[row] = nf;
}

// ---------------- final: manlin(W2) + mob_relu + residual -> fp32 out ----------------
__global__ void __launch_bounds__(256) manlin_final_w(
    const float* __restrict__ mx, const float* __restrict__ xnb,
    const float* __restrict__ bias, int b2idx, const float* __restrict__ resid,
    float* __restrict__ outf)
{
    const int lane = threadIdx.x & 31;
    const size_t row = blockIdx.x * 8 + (threadIdx.x >> 5);
    const float MAXN = maxnorm();
    float4 v[4], bvv[4];
    float ss = 0.0f;
    #pragma unroll
    for (int i = 0; i < 4; i++) {
        v[i] = ((const float4*)(mx + row*ED))[lane + i*32];
        bvv[i] = ((const float4*)bias)[lane + i*32];
        ss += sq4(v[i]);
    }
    float mxn = sqrtf(warpSumF(ss) + 1e-30f);
    float xn = xnb[row];
    float s = tanhf(mxn / xn * atanhf(fminf(xn, MAXN))) / mxn;
    float dxy = 0.0f, dx2 = 0.0f;
    #pragma unroll
    for (int i = 0; i < 4; i++) {
        v[i] = scl4(v[i], s);
        dxy += dot4(v[i], bvv[i]);
        dx2 += sq4(v[i]);
    }
    float xy = warpSumF(dxy);
    float x2 = warpSumF(dx2);
    float y2 = g_b2[b2idx];
    float a = 1.0f + 2.0f*xy + y2;
    float c = 1.0f - x2;
    float invd = 1.0f / fmaxf(1.0f + 2.0f*xy + x2*y2, 1e-15f);
    float zz = 0.0f;
    #pragma unroll
    for (int i = 0; i < 4; i++) {
        VOP4(v[i], (a*v[i].x + c*bvv[i].x)*invd, (a*v[i].y + c*bvv[i].y)*invd,
                   (a*v[i].z + c*bvv[i].z)*invd, (a*v[i].w + c*bvv[i].w)*invd);
        zz += sq4(v[i]);
    }
    {
        float zn = sqrtf(warpSumF(zz) + 1e-30f);
        if (zn > MAXN) { float ps = MAXN / zn;
            #pragma unroll
            for (int i = 0; i < 4; i++) v[i] = scl4(v[i], ps); }
    }
    {
        float s0 = 0.0f;
        #pragma unroll
        for (int i = 0; i < 4; i++) s0 += sq4(v[i]);
        float n = sqrtf(warpSumF(s0) + 1e-30f);
        float lf = atanhf(fminf(n, MAXN)) / n;
        float s1 = 0.0f;
        #pragma unroll
        for (int i = 0; i < 4; i++) {
            VOP4(v[i], fmaxf(lf*v[i].x, 0.0f), fmaxf(lf*v[i].y, 0.0f),
                       fmaxf(lf*v[i].z, 0.0f), fmaxf(lf*v[i].w, 0.0f));
            s1 += sq4(v[i]);
        }
        float nr = sqrtf(warpSumF(s1) + 1e-30f);
        float ef = tanhf(nr) / nr;
        float s2 = 0.0f;
        #pragma unroll
        for (int i = 0; i < 4; i++) { v[i] = scl4(v[i], ef); s2 += sq4(v[i]); }
        float n2 = sqrtf(warpSumF(s2) + 1e-30f);
        if (n2 > MAXN) { float ps = MAXN / n2;
            #pragma unroll
            for (int i = 0; i < 4; i++) v[i] = scl4(v[i], ps); }
    }
    {
        float d1 = 0.0f, d2 = 0.0f, d3 = 0.0f;
        float4 rv[4];
        #pragma unroll
        for (int i = 0; i < 4; i++) {
            rv[i] = ((const float4*)(resid + row*ED))[lane + i*32];
            d1 += dot4(v[i], rv[i]);
            d2 += sq4(rv[i]);
            d3 += sq4(v[i]);
        }
        float rxy = warpSumF(d1);
        float ry2 = warpSumF(d2);
        float rx2 = warpSumF(d3);
        float ra = 1.0f + 2.0f*rxy + ry2;
        float rc = 1.0f - rx2;
        float rinv = 1.0f / fmaxf(1.0f + 2.0f*rxy + rx2*ry2, 1e-15f);
        float s3 = 0.0f;
        #pragma unroll
        for (int i = 0; i < 4; i++) {
            VOP4(v[i], (ra*v[i].x + rc*rv[i].x)*rinv, (ra*v[i].y + rc*rv[i].y)*rinv,
                       (ra*v[i].z + rc*rv[i].z)*rinv, (ra*v[i].w + rc*rv[i].w)*rinv);
            s3 += sq4(v[i]);
        }
        float zn = sqrtf(warpSumF(s3) + 1e-30f);
        if (zn > MAXN) { float ps = MAXN / zn;
            #pragma unroll
            for (int i = 0; i < 4; i++) v[i] = scl4(v[i], ps); }
    }
    #pragma unroll
    for (int i = 0; i < 4; i++) ((float4*)(outf + row*ED))[lane + i*32] = v[i];
}

// ---------------- MMA helpers ----------------
__device__ __forceinline__ void ldsm_x4(uint32_t &r0, uint32_t &r1, uint32_t &r2, uint32_t &r3, uint32_t addr) {
    asm volatile("ldmatrix.sync.aligned.m8n8.x4.shared.b16 {%0,%1,%2,%3}, [%4];"
                 : "=r"(r0), "=r"(r1), "=r"(r2), "=r"(r3) : "r"(addr));
}
__device__ __forceinline__ void ldsm_x4t(uint32_t &r0, uint32_t &r1, uint32_t &r2, uint32_t &r3, uint32_t addr) {
    asm volatile("ldmatrix.sync.aligned.m8n8.x4.trans.shared.b16 {%0,%1,%2,%3}, [%4];"
                 : "=r"(r0), "=r"(r1), "=r"(r2), "=r"(r3) : "r"(addr));
}
__device__ __forceinline__ void mma16816(float* c, const uint32_t* a, const uint32_t* b) {
    asm volatile("mma.sync.aligned.m16n8k16.row.col.f32.bf16.bf16.f32 "
                 "{%0,%1,%2,%3}, {%4,%5,%6,%7}, {%8,%9}, {%0,%1,%2,%3};"
                 : "+f"(c[0]), "+f"(c[1]), "+f"(c[2]), "+f"(c[3])
                 : "r"(a[0]), "r"(a[1]), "r"(a[2]), "r"(a[3]), "r"(b[0]), "r"(b[1]));
}
#define CP_ASYNC16(dst, src) asm volatile("cp.async.cg.shared.global [%0], [%1], 16;" :: "r"(dst), "l"(src))

// ---------------- tensor-core attention: Q/K/V in 96KB smem, 2 CTAs/SM, max-free softmax ----------------
#define ATT_SMEM 98304
__global__ void __launch_bounds__(256, 2) attn_mma(
    const __nv_bfloat16* __restrict__ qh_g, const __nv_bfloat16* __restrict__ ql_g,
    float* __restrict__ o)
{
    extern __shared__ __nv_bfloat16 smbuf[];
    uint32_t smb = (uint32_t)__cvta_generic_to_shared(smbuf);
    const int tid = threadIdx.x;
    const int lane = tid & 31, w = tid >> 5;
    const int bh = blockIdx.x, b = bh >> 3, h = bh & 7;

    #pragma unroll
    for (int it = 0; it < 24; it++) {
        int idx = tid + (it << 8);
        int tensor = idx >> 10;
        int cid = idx & 1023;
        int r = cid >> 3, c = cid & 7;
        uint32_t dst = smb + tensor*16384 + r*128 + ((c ^ (r & 7)) << 4);
        const __nv_bfloat16* P = (tensor & 1) ? ql_g : qh_g;
        const __nv_bfloat16* src = P + ((size_t)r*BB + b)*QKVW + (size_t)(tensor>>1)*512 + h*HD + c*8;
        CP_ASYNC16(dst, src);
    }
    asm volatile("cp.async.commit_group;");
    asm volatile("cp.async.wait_group 0;");
    __syncthreads();

    const int quad = lane >> 3, r8 = lane & 7;

    float sc[16][4];
    #pragma unroll
    for (int n = 0; n < 16; n++)
        #pragma unroll
        for (int e = 0; e < 4; e++) sc[n][e] = 0.0f;

    #pragma unroll
    for (int kk = 0; kk < 4; kk++) {
        uint32_t qh_[4], ql_[4];
        int arow = w*16 + (quad & 1)*8 + r8;
        int achk = kk*2 + (quad >> 1);
        uint32_t aoff = (uint32_t)(arow*128 + ((achk ^ (arow & 7)) << 4));
        ldsm_x4(qh_[0], qh_[1], qh_[2], qh_[3], smb + aoff);
        ldsm_x4(ql_[0], ql_[1], ql_[2], ql_[3], smb + 16384 + aoff);
        #pragma unroll
        for (int nn = 0; nn < 8; nn++) {
            int krow = nn*16 + (quad >> 1)*8 + r8;
            int kchk = kk*2 + (quad & 1);
            uint32_t koff = (uint32_t)(krow*128 + ((kchk ^ (krow & 7)) << 4));
            uint32_t kh0[2], kh1[2], kl0[2], kl1[2];
            { uint32_t a0,a1,a2,a3; ldsm_x4(a0,a1,a2,a3, smb + 32768 + koff);
              kh0[0]=a0; kh0[1]=a1; kh1[0]=a2; kh1[1]=a3; }
            { uint32_t a0,a1,a2,a3; ldsm_x4(a0,a1,a2,a3, smb + 49152 + koff);
              kl0[0]=a0; kl0[1]=a1; kl1[0]=a2; kl1[1]=a3; }
            mma16816(sc[2*nn],   qh_, kh0);
            mma16816(sc[2*nn],   qh_, kl0);
            mma16816(sc[2*nn],   ql_, kh0);
            mma16816(sc[2*nn+1], qh_, kh1);
            mma16816(sc[2*nn+1], qh_, kl1);
            mma16816(sc[2*nn+1], ql_, kh1);
        }
    }

    // max-free softmax: scores bounded (|s| <= atanh(1-1e-5)^2 ~ 37.5), exp(s/8) safe in fp32
    float l0 = 0.0f, l1 = 0.0f;
    #pragma unroll
    for (int n = 0; n < 16; n++) {
        sc[n][0] = fexp8(sc[n][0]); l0 += sc[n][0];
        sc[n][1] = fexp8(sc[n][1]); l0 += sc[n][1];
        sc[n][2] = fexp8(sc[n][2]); l1 += sc[n][2];
        sc[n][3] = fexp8(sc[n][3]); l1 += sc[n][3];
    }
    l0 += __shfl_xor_sync(0xffffffffu, l0, 1);
    l0 += __shfl_xor_sync(0xffffffffu, l0, 2);
    l1 += __shfl_xor_sync(0xffffffffu, l1, 1);
    l1 += __shfl_xor_sync(0xffffffffu, l1, 2);
    float inv0 = 1.0f / l0, inv1 = 1.0f / l1;

    float oa[8][4];
    #pragma unroll
    for (int n = 0; n < 8; n++)
        #pragma unroll
        for (int e = 0; e < 4; e++) oa[n][e] = 0.0f;

    #pragma unroll
    for (int kt = 0; kt < 8; kt++) {
        uint32_t ph[4], pl[4];
        #pragma unroll
        for (int half = 0; half < 2; half++) {
            int n2 = 2*kt + half;
            float p0 = sc[n2][0], p1 = sc[n2][1], p2 = sc[n2][2], p3 = sc[n2][3];
            __nv_bfloat16 b0 = __float2bfloat16(p0), b1 = __float2bfloat16(p1);
            __nv_bfloat16 b2 = __float2bfloat16(p2), b3 = __float2bfloat16(p3);
            ph[half*2+0] = pack_bf2(p0, p1);
            ph[half*2+1] = pack_bf2(p2, p3);
            pl[half*2+0] = pack_bf2(p0 - __bfloat162float(b0), p1 - __bfloat162float(b1));
            pl[half*2+1] = pack_bf2(p2 - __bfloat162float(b2), p3 - __bfloat162float(b3));
        }
        #pragma unroll
        for (int nn = 0; nn < 4; nn++) {
            int vrow = kt*16 + (quad & 1)*8 + r8;
            int vchk = 2*nn + (quad >> 1);
            uint32_t voff = (uint32_t)(vrow*128 + ((vchk ^ (vrow & 7)) << 4));
            uint32_t vh0[2], vh1[2], vl0[2], vl1[2];
            { uint32_t a0,a1,a2,a3; ldsm_x4t(a0,a1,a2,a3, smb + 65536 + voff);
              vh0[0]=a0; vh0[1]=a1; vh1[0]=a2; vh1[1]=a3; }
            { uint32_t a0,a1,a2,a3; ldsm_x4t(a0,a1,a2,a3, smb + 81920 + voff);
              vl0[0]=a0; vl0[1]=a1; vl1[0]=a2; vl1[1]=a3; }
            mma16816(oa[2*nn],   ph, vh0);
            mma16816(oa[2*nn],   ph, vl0);
            mma16816(oa[2*nn],   pl, vh0);
            mma16816(oa[2*nn+1], ph, vh1);
            mma16816(oa[2*nn+1], ph, vl1);
            mma16816(oa[2*nn+1], pl, vh1);
        }
    }

    int g = lane >> 2, t2 = (lane & 3) * 2;
    int t0 = w*16 + g;
    #pragma unroll
    for (int n = 0; n < 8; n++) {
        size_t base0 = ((size_t)t0*BB + b)*ED + (size_t)h*HD + n*8 + t2;
        size_t base1 = ((size_t)(t0+8)*BB + b)*ED + (size_t)h*HD + n*8 + t2;
        *(float2*)(o + base0) = make_float2(oa[n][0]*inv0, oa[n][1]*inv0);
        *(float2*)(o + base1) = make_float2(oa[n][2]*inv1, oa[n][3]*inv1);
    }
}

// ================= bf16x3 HMMA GEMM (R13 scheduling: interleaved A/B loads) =================
#define BM 128
#define BN 128
#define BK 32
#define TEN_B   8192
#define STAGE_B (4*TEN_B)
#define GEMM_SMEM (3*STAGE_B)

__device__ __forceinline__ uint32_t saddr(int r, int colElem) {
    return (uint32_t)(r*64 + ((((colElem >> 3) ^ ((r >> 1) & 3))) << 4));
}

__global__ void __launch_bounds__(256, 2) gemm_bf16x3(
    const __nv_bfloat16* __restrict__ Ah, const __nv_bfloat16* __restrict__ Al,
    const __nv_bfloat16* __restrict__ Wh, const __nv_bfloat16* __restrict__ Wl,
    float* __restrict__ C, int M, int N, int K)
{
    extern __shared__ __nv_bfloat16 smbuf[];
    const int tid = threadIdx.x;
    const int lane = tid & 31, w = tid >> 5;
    const int wm = w & 1, wn = w >> 1;
    const int rowBase = blockIdx.y * BM;
    const int colBase = blockIdx.x * BN;
    uint32_t smbase = (uint32_t)__cvta_generic_to_shared(smbuf);

    float acc[4][4][4];
    #pragma unroll
    for (int i = 0; i < 4; i++)
        #pragma unroll
        for (int j = 0; j < 4; j++)
            #pragma unroll
            for (int e = 0; e < 4; e++) acc[i][j][e] = 0.0f;

    auto load_stage = [&](int st, int k0) {
        uint32_t base = smbase + st * STAGE_B;
        #pragma unroll
        for (int it = 0; it < 8; it++) {
            int idx = tid + (it << 8);
            int tensor = idx >> 9;
            int cid = idx & 511;
            int r = cid >> 2, c = cid & 3;
            uint32_t dst = base + tensor * TEN_B
                         + (uint32_t)(r*64 + ((c ^ ((r >> 1) & 3)) << 4));
            const __nv_bfloat16* src;
            if (tensor == 0)      src = Ah + (size_t)(rowBase + r) * K + k0 + c * 8;
            else if (tensor == 1) src = Al + (size_t)(rowBase + r) * K + k0 + c * 8;
            else if (tensor == 2) src = Wh + (size_t)(colBase + r) * K + k0 + c * 8;
            else                  src = Wl + (size_t)(colBase + r) * K + k0 + c * 8;
            CP_ASYNC16(dst, src);
        }
        asm volatile("cp.async.commit_group;");
    };

    auto compute_stage = [&](int st) {
        uint32_t base = smbase + st * STAGE_B;
        uint32_t aH = base;
        uint32_t aL = base + 1*TEN_B;
        uint32_t wH = base + 2*TEN_B;
        uint32_t wL = base + 3*TEN_B;
        const int quad = lane >> 3, r8 = lane & 7;
        #pragma unroll
        for (int kk = 0; kk < BK; kk += 16) {
            uint32_t ah[4][4], al[4][4], bh[4][2], bl[4][2];
            #pragma unroll
            for (int i = 0; i < 4; i++) {
                int row = wm*64 + i*16 + (quad & 1)*8 + r8;
                int col = kk + (quad >> 1)*8;
                uint32_t off = saddr(row, col);
                ldsm_x4(ah[i][0], ah[i][1], ah[i][2], ah[i][3], aH + off);
                ldsm_x4(al[i][0], al[i][1], al[i][2], al[i][3], aL + off);
            }
            #pragma unroll
            for (int jj = 0; jj < 2; jj++) {
                int nr = wn*32 + jj*16 + (quad >> 1)*8 + r8;
                int kc = kk + (quad & 1)*8;
                uint32_t off = saddr(nr, kc);
                uint32_t a0,a1,a2,a3;
                ldsm_x4(a0,a1,a2,a3, wH + off);
                bh[2*jj][0]=a0; bh[2*jj][1]=a1; bh[2*jj+1][0]=a2; bh[2*jj+1][1]=a3;
                ldsm_x4(a0,a1,a2,a3, wL + off);
                bl[2*jj][0]=a0; bl[2*jj][1]=a1; bl[2*jj+1][0]=a2; bl[2*jj+1][1]=a3;
            }
            #pragma unroll
            for (int i = 0; i < 4; i++)
                #pragma unroll
                for (int j = 0; j < 4; j++) mma16816(acc[i][j], ah[i], bh[j]);
            #pragma unroll
            for (int i = 0; i < 4; i++)
                #pragma unroll
                for (int j = 0; j < 4; j++) mma16816(acc[i][j], ah[i], bl[j]);
            #pragma unroll
            for (int i = 0; i < 4; i++)
                #pragma unroll
                for (int j = 0; j < 4; j++) mma16816(acc[i][j], al[i], bh[j]);
        }
    };

    const int nkb = K / BK;
    load_stage(0, 0);
    load_stage(1, BK);
    for (int kb = 0; kb < nkb; kb++) {
        if (kb == nkb - 1) { asm volatile("cp.async.wait_group 0;"); }
        else               { asm volatile("cp.async.wait_group 1;"); }
        __syncthreads();
        if (kb + 2 < nkb) load_stage((kb + 2) % 3, (kb + 2) * BK);
        compute_stage(kb % 3);
    }

    const int g = lane >> 2, tg = lane & 3;
    #pragma unroll
    for (int i = 0; i < 4; i++) {
        int row = rowBase + wm*64 + i*16 + g;
        #pragma unroll
        for (int j = 0; j < 4; j++) {
            int col = colBase + wn*32 + j*8 + tg*2;
            *(float2*)(C + (size_t)row * N + col)       = make_float2(acc[i][j][0], acc[i][j][1]);
            *(float2*)(C + (size_t)(row + 8) * N + col) = make_float2(acc[i][j][2], acc[i][j][3]);
        }
    }
}

// ---------------- launch ----------------
extern "C" void kernel_launch(void* const* d_in, const int* in_sizes, int n_in,
                              void* d_out, int out_size)
{
    const float* x    = (const float*)d_in[0];
    const float* l1g  = (const float*)d_in[1];
    const float* l1b  = (const float*)d_in[2];
    const float* l2g  = (const float*)d_in[3];
    const float* l2b  = (const float*)d_in[4];
    const float* Wq   = (const float*)d_in[5];
    const float* bq   = (const float*)d_in[6];
    const float* Wk   = (const float*)d_in[7];
    const float* bk   = (const float*)d_in[8];
    const float* Wv   = (const float*)d_in[9];
    const float* bv   = (const float*)d_in[10];
    const float* Wo   = (const float*)d_in[11];
    const float* bo   = (const float*)d_in[12];
    const float* W1   = (const float*)d_in[13];
    const float* b1   = (const float*)d_in[14];
    const float* W2   = (const float*)d_in[15];
    const float* b2   = (const float*)d_in[16];
    float* out = (float*)d_out;

    float *qkv, *ob, *h1, *big, *n0, *no, *nh2, *nh3, *bsq;
    __nv_bfloat16 *xh, *xl, *wh, *wl;
    cudaGetSymbolAddress((void**)&qkv, g_qkv);
    cudaGetSymbolAddress((void**)&ob,  g_o);
    cudaGetSymbolAddress((void**)&h1,  g_h1);
    cudaGetSymbolAddress((void**)&big, g_big);
    cudaGetSymbolAddress((void**)&xh,  g_xh);
    cudaGetSymbolAddress((void**)&xl,  g_xl);
    cudaGetSymbolAddress((void**)&wh,  g_wh);
    cudaGetSymbolAddress((void**)&wl,  g_wl);
    cudaGetSymbolAddress((void**)&n0,  g_n0);
    cudaGetSymbolAddress((void**)&no,  g_no);
    cudaGetSymbolAddress((void**)&nh2, g_nh2);
    cudaGetSymbolAddress((void**)&nh3, g_nh3);
    cudaGetSymbolAddress((void**)&bsq, g_b2);

    cudaFuncSetAttribute(gemm_bf16x3, cudaFuncAttributeMaxDynamicSharedMemorySize, GEMM_SMEM);
    cudaFuncSetAttribute(attn_mma, cudaFuncAttributeMaxDynamicSharedMemorySize, ATT_SMEM);

    prep_kernel<<<PREP_BLOCKS, 256>>>(Wq, Wk, Wv, Wo, W1, W2,
                                      bq, bk, bv, bo, b1, b2,
                                      x, l1g, l1b, wh, wl, xh, xl, n0, bsq);

    gemm_bf16x3<<<dim3(QKVW/BN, NR/BM), 256, GEMM_SMEM>>>(xh, xl, wh + WQ0, wl + WQ0, qkv, NR, QKVW, ED);
    manlin_qkv_w<<<dim3(NR/8, 3), 256>>>(qkv, n0, bq, bk, bv, xh, xl);

    attn_mma<<<BB * NH, 256, ATT_SMEM>>>(xh, xl, ob);
    expmap_w<<<NR/8, 256>>>(ob, xh, xl, no);

    gemm_bf16x3<<<dim3(ED/BN, NR/BM), 256, GEMM_SMEM>>>(xh, xl, wh + WO0, wl + WO0, big, NR, ED, ED);
    manlin_ln_w<<<NR/8, 256>>>(big, no, bo, 3, x, h1, l2g, l2b, xh, xl, nh2);

    gemm_bf16x3<<<dim3(FD/BN, NR/BM), 256, GEMM_SMEM>>>(xh, xl, wh + W10, wl + W10, big, NR, FD, ED);
    manlin_fc1_w<<<NR/4, 128>>>(big, nh2, b1, xh, xl, nh3);

    gemm_bf16x3<<<dim3(ED/BN, NR/BM), 256, GEMM_SMEM>>>(xh, xl, wh + W20, wl + W20, qkv, NR, ED, FD);
    manlin_final_w<<<NR/8, 256>>>(qkv, nh3, b2, 5, h1, out);
}